// round 1
// baseline (speedup 1.0000x reference)
#include <cuda_runtime.h>
#include <math.h>

#define B   32
#define L   64
#define DQ  1024
#define C   512
#define NH  8
#define DK  64
#define HW  1024
#define TEMP_INV 0.125f   // 1/sqrt(64)

// ---------------- scratch (no allocations allowed) ----------------
__device__ __align__(16) float g_qs  [B*DQ];
__device__ __align__(16) float g_qsum[B*C];
__device__ __align__(16) float g_wqc [B*NH*C];
__device__ __align__(16) float g_wqd [B*NH*C];
__device__              float g_bqc [B*NH];
__device__              float g_bqd [B*NH];
__device__ __align__(16) float g_score[B*NH*HW];
__device__ __align__(16) float g_p   [B*NH*HW];
__device__ __align__(16) float g_dif [B*NH*HW];
__device__ __align__(16) float g_vbar[B*NH*C];
__device__ __align__(16) float g_attn[B*C];
__device__              float g_A9  [B*NH*9];

// ---- K1: qs[b,dq] = sum_l q[b,l,dq] ----
__global__ void k_qsum_l(const float* __restrict__ q) {
    int b = blockIdx.x, d = threadIdx.x;
    const float* p = q + (size_t)b * L * DQ + d;
    float s = 0.f;
#pragma unroll
    for (int l = 0; l < L; l++) s += p[l * DQ];
    g_qs[b * DQ + d] = s;
}

// ---- K2: q_sum[b,o] = qs[b,:] . w_qs_w[o,:] + L*bias[o] ----
__global__ void k_qproj(const float* __restrict__ w, const float* __restrict__ bias) {
    __shared__ __align__(16) float sq[DQ];
    int b = blockIdx.x, o = threadIdx.x;  // 512 threads
    sq[o]       = g_qs[b * DQ + o];
    sq[o + 512] = g_qs[b * DQ + o + 512];
    __syncthreads();
    const float4* wr  = (const float4*)(w + (size_t)o * DQ);
    const float4* sq4 = (const float4*)sq;
    float acc = (float)L * bias[o];
#pragma unroll 4
    for (int k = 0; k < DQ / 4; k++) {
        float4 a = wr[k], x = sq4[k];
        acc += a.x * x.x + a.y * x.y + a.z * x.z + a.w * x.w;
    }
    g_qsum[b * C + o] = acc;
}

// ---- K3: wq_c[b,n,c] = sum_d w_kc[n*64+d, c] * q_sum[b, n*64+d]; plus bias dots ----
__global__ void k_wq(const float* __restrict__ wkc, const float* __restrict__ bkc,
                     const float* __restrict__ wkd, const float* __restrict__ bkd) {
    __shared__ float sh[DK], pc[DK], pd[DK];
    int bn = blockIdx.x;            // b*8+n
    int n = bn & 7;
    int b = bn >> 3;
    int c = threadIdx.x;            // 512
    if (c < DK) sh[c] = g_qsum[b * C + n * DK + c];
    __syncthreads();
    float ac = 0.f, ad = 0.f;
#pragma unroll 8
    for (int d = 0; d < DK; d++) {
        float qv = sh[d];
        ac += wkc[(size_t)(n * DK + d) * C + c] * qv;
        ad += wkd[(size_t)(n * DK + d) * C + c] * qv;
    }
    g_wqc[(size_t)bn * C + c] = ac;
    g_wqd[(size_t)bn * C + c] = ad;
    if (c < DK) { pc[c] = bkc[n * DK + c] * sh[c]; pd[c] = bkd[n * DK + c] * sh[c]; }
    __syncthreads();
    if (c == 0) {
        float s1 = 0.f, s2 = 0.f;
        for (int d = 0; d < DK; d++) { s1 += pc[d]; s2 += pd[d]; }
        g_bqc[bn] = s1; g_bqd[bn] = s2;
    }
}

// ---- K4a: score_c[b,n,s], dif[b,n,s]=sigmoid(score_d) ----
__global__ void k_scores(const float* __restrict__ v) {
    __shared__ __align__(16) float swc[NH * C];
    __shared__ __align__(16) float swd[NH * C];
    int b = blockIdx.x;
    int s = blockIdx.y * 256 + threadIdx.x;
    const float4* gc = (const float4*)(g_wqc + (size_t)b * NH * C);
    const float4* gd = (const float4*)(g_wqd + (size_t)b * NH * C);
    float4* sc4 = (float4*)swc; float4* sd4 = (float4*)swd;
    for (int i = threadIdx.x; i < NH * C / 4; i += 256) { sc4[i] = gc[i]; sd4[i] = gd[i]; }
    __syncthreads();
    float ac[NH], ad[NH];
#pragma unroll
    for (int n = 0; n < NH; n++) { ac[n] = 0.f; ad[n] = 0.f; }
    const float* vp = v + (size_t)b * C * HW + s;
    for (int c = 0; c < C; c++) {
        float vv = vp[(size_t)c * HW];
#pragma unroll
        for (int n = 0; n < NH; n++) {
            ac[n] += vv * swc[n * C + c];
            ad[n] += vv * swd[n * C + c];
        }
    }
#pragma unroll
    for (int n = 0; n < NH; n++) {
        int bn = b * NH + n;
        g_score[(size_t)bn * HW + s] = (ac[n] + g_bqc[bn]) * TEMP_INV;
        float x = (ad[n] + g_bqd[bn]) * TEMP_INV;
        g_dif[(size_t)bn * HW + s] = 1.f / (1.f + expf(-x));
    }
}

// ---- K4b: p = softmax_s(score_c) ----
__global__ void k_softmax() {
    __shared__ float red[8];
    int bn = blockIdx.x, t = threadIdx.x;    // 256 threads, 4 s each
    const float4* sc = (const float4*)(g_score + (size_t)bn * HW);
    float4 x = sc[t];
    float m = fmaxf(fmaxf(x.x, x.y), fmaxf(x.z, x.w));
#pragma unroll
    for (int o = 16; o; o >>= 1) m = fmaxf(m, __shfl_xor_sync(0xffffffffu, m, o));
    if ((t & 31) == 0) red[t >> 5] = m;
    __syncthreads();
    float M = red[0];
#pragma unroll
    for (int i = 1; i < 8; i++) M = fmaxf(M, red[i]);
    float e0 = expf(x.x - M), e1 = expf(x.y - M), e2 = expf(x.z - M), e3 = expf(x.w - M);
    float s = e0 + e1 + e2 + e3;
#pragma unroll
    for (int o = 16; o; o >>= 1) s += __shfl_xor_sync(0xffffffffu, s, o);
    __syncthreads();
    if ((t & 31) == 0) red[t >> 5] = s;
    __syncthreads();
    float S = 0.f;
#pragma unroll
    for (int i = 0; i < 8; i++) S += red[i];
    float inv = 1.f / S;
    float4 o4 = make_float4(e0 * inv, e1 * inv, e2 * inv, e3 * inv);
    ((float4*)(g_p + (size_t)bn * HW))[t] = o4;
}

// ---- K5: vbar[b,n,c] = sum_s p[b,n,s] * v[b,c,s] ----
__global__ void k_vbar(const float* __restrict__ v) {
    __shared__ __align__(16) float sp[NH * HW];
    int b = blockIdx.x;
    const float4* gp = (const float4*)(g_p + (size_t)b * NH * HW);
    float4* sp4 = (float4*)sp;
    for (int i = threadIdx.x; i < NH * HW / 4; i += 512) sp4[i] = gp[i];
    __syncthreads();
    int warp = threadIdx.x >> 5, lane = threadIdx.x & 31;
    for (int pass = 0; pass < 8; pass++) {
        int c = blockIdx.y * 128 + pass * 16 + warp;
        const float* vp = v + (size_t)(b * C + c) * HW;
        float acc[NH];
#pragma unroll
        for (int n = 0; n < NH; n++) acc[n] = 0.f;
        for (int it = 0; it < 32; it++) {
            int s = lane + it * 32;
            float vv = vp[s];
#pragma unroll
            for (int n = 0; n < NH; n++) acc[n] += vv * sp[n * HW + s];
        }
#pragma unroll
        for (int n = 0; n < NH; n++) {
#pragma unroll
            for (int o = 16; o; o >>= 1) acc[n] += __shfl_xor_sync(0xffffffffu, acc[n], o);
        }
        if (lane == 0) {
#pragma unroll
            for (int n = 0; n < NH; n++) g_vbar[(size_t)(b * NH + n) * C + c] = acc[n];
        }
    }
}

// ---- K6: attn[b,o] = w_vs[o,:].vbar[b,head(o),:]+bias; A9[b,n,9] factorized conv taps ----
__global__ void k_attn(const float* __restrict__ wvs, const float* __restrict__ bvs,
                       const float* __restrict__ wm) {
    __shared__ __align__(16) float svb[NH * C];
    __shared__ float sa[C];
    int b = blockIdx.x, o = threadIdx.x, n = o >> 6;
    const float4* gv = (const float4*)(g_vbar + (size_t)b * NH * C);
    float4* s4 = (float4*)svb;
    for (int i = o; i < NH * C / 4; i += 512) s4[i] = gv[i];
    __syncthreads();
    const float* wr = wvs + (size_t)o * C;
    const float* vb = svb + n * C;
    float acc = bvs[o];
#pragma unroll 4
    for (int c = 0; c < C; c++) acc += wr[c] * vb[c];
    sa[o] = acc;
    g_attn[b * C + o] = acc;
    __syncthreads();
    if (o < NH * 9) {
        int nn = o / 9, k = o - nn * 9;
        float a = 0.f;
        for (int d = 0; d < DK; d++) a += sa[nn * DK + d] * wm[(size_t)(nn * DK + d) * 9 + k];
        g_A9[b * NH * 9 + o] = a;
    }
}

// ---- K7: out + attn_map (the big streamer) ----
// out[b,c,i,j] = dif[b,n, j*32+i] * attn[b,n,d]; attn_map = same; out gets BN+res+leaky
__global__ void k_out(const float* __restrict__ v, const float* __restrict__ gam,
                      const float* __restrict__ bet, const float* __restrict__ mean,
                      const float* __restrict__ var, float* __restrict__ out,
                      float* __restrict__ amap) {
    __shared__ float sd[HW + HW / 32];   // padded: s -> s + (s>>5)
    int bc = blockIdx.x;                  // b*512 + c
    int b = bc >> 9, c = bc & 511, n = c >> 6;
    int t4 = threadIdx.x * 4;
    const float* gdif = g_dif + (size_t)(b * NH + n) * HW;
#pragma unroll
    for (int u = 0; u < 4; u++) { int s = t4 + u; sd[s + (s >> 5)] = gdif[s]; }
    float a  = g_attn[b * C + c];
    float sc = gam[c] * rsqrtf(var[c] + 1e-5f);
    float mn = mean[c], bt = bet[c];
    __syncthreads();
    size_t base = (size_t)bc * HW + t4;
    float4 rv = *(const float4*)(v + base);
    const float* rvp = (const float*)&rv;
    float vals[4], os[4];
#pragma unroll
    for (int u = 0; u < 4; u++) {
        int t = t4 + u;
        int i = t >> 5, j = t & 31;
        float dd = sd[j * 33 + i];   // padded transpose read, conflict-free
        float val = dd * a;
        vals[u] = val;
        float o2 = (val - mn) * sc + bt + rvp[u];
        os[u] = o2 >= 0.f ? o2 : 0.1f * o2;
    }
    *(float4*)(amap + base) = *(float4*)vals;
    *(float4*)(out  + base) = *(float4*)os;
}

// ---- K8: m_attn[b, i*32+j] = bias + sum_{n,ki,kj} A9 * difT(padded window) ----
__global__ void k_m(const float* __restrict__ wmb, float* __restrict__ m) {
    __shared__ float sd[NH][HW + 32];
    __shared__ float sA[NH * 9];
    int b = blockIdx.x, t = threadIdx.x;   // 1024 threads
    for (int n = 0; n < NH; n++) { int s = t; sd[n][s + (s >> 5)] = g_dif[(size_t)(b * NH + n) * HW + s]; }
    if (t < NH * 9) sA[t] = g_A9[b * NH * 9 + t];
    __syncthreads();
    int i = t >> 5, j = t & 31;
    float acc = wmb[0];
#pragma unroll
    for (int n = 0; n < NH; n++) {
#pragma unroll
        for (int ki = 0; ki < 3; ki++) {
            int ii = i + ki - 1;
            if (ii < 0 || ii >= 32) continue;
#pragma unroll
            for (int kj = 0; kj < 3; kj++) {
                int jj = j + kj - 1;
                if (jj < 0 || jj >= 32) continue;
                acc += sA[n * 9 + ki * 3 + kj] * sd[n][jj * 33 + ii];
            }
        }
    }
    m[b * HW + i * 32 + j] = acc;
}

extern "C" void kernel_launch(void* const* d_in, const int* in_sizes, int n_in,
                              void* d_out, int out_size) {
    (void)in_sizes; (void)n_in; (void)out_size;
    const float* q      = (const float*)d_in[0];
    const float* v      = (const float*)d_in[1];
    // d_in[2] = mask — provably unused (softmax over size-1 axis == 1)
    const float* w_qs_w = (const float*)d_in[3];
    const float* w_qs_b = (const float*)d_in[4];
    // d_in[5], d_in[6] = w_qs_att_* — unused for the same reason
    const float* w_kc_w = (const float*)d_in[7];
    const float* w_kc_b = (const float*)d_in[8];
    const float* w_kd_w = (const float*)d_in[9];
    const float* w_kd_b = (const float*)d_in[10];
    const float* w_vs_w = (const float*)d_in[11];
    const float* w_vs_b = (const float*)d_in[12];
    const float* w_m_w  = (const float*)d_in[13];
    const float* w_m_b  = (const float*)d_in[14];
    const float* bn_g   = (const float*)d_in[15];
    const float* bn_b   = (const float*)d_in[16];
    const float* bn_m   = (const float*)d_in[17];
    const float* bn_v   = (const float*)d_in[18];

    float* out    = (float*)d_out;
    float* m_attn = out + (size_t)B * C * HW;        // 16,777,216
    float* amap   = m_attn + (size_t)B * HW;         // +32,768

    k_qsum_l <<<B, 1024>>>(q);
    k_qproj  <<<B, 512>>>(w_qs_w, w_qs_b);
    k_wq     <<<B * NH, 512>>>(w_kc_w, w_kc_b, w_kd_w, w_kd_b);
    k_scores <<<dim3(B, 4), 256>>>(v);
    k_softmax<<<B * NH, 256>>>();
    k_vbar   <<<dim3(B, 4), 512>>>(v);
    k_attn   <<<B, 512>>>(w_vs_w, w_vs_b, w_m_w);
    k_out    <<<B * C, 256>>>(v, bn_g, bn_b, bn_m, bn_v, out, amap);
    k_m      <<<B, 1024>>>(w_m_b, m_attn);
}

// round 2
// speedup vs baseline: 1.0931x; 1.0931x over previous
#include <cuda_runtime.h>
#include <math.h>

#define B   32
#define L   64
#define DQ  1024
#define C   512
#define NH  8
#define DK  64
#define HW  1024
#define TEMP_INV 0.125f   // 1/sqrt(64)

// ---------------- scratch (no allocations allowed) ----------------
__device__ __align__(16) float g_qs  [B*DQ];
__device__ __align__(16) float g_qsum[B*C];
__device__ __align__(16) float g_wqc [B*NH*C];
__device__ __align__(16) float g_wqd [B*NH*C];
__device__              float g_bqc [B*NH];
__device__              float g_bqd [B*NH];
__device__ __align__(16) float g_score[B*NH*HW];
__device__ __align__(16) float g_p   [B*NH*HW];
__device__ __align__(16) float g_dif [B*NH*HW];
__device__ __align__(16) float g_vbar[B*NH*C];
__device__ __align__(16) float g_attn[B*C];

// ---- K1: qs[b,dq] = sum_l q[b,l,dq] ----
__global__ void k_qsum_l(const float* __restrict__ q) {
    int b = blockIdx.x;
    int d = blockIdx.y * 512 + threadIdx.x;
    const float* p = q + (size_t)b * L * DQ + d;
    float s = 0.f;
#pragma unroll
    for (int l = 0; l < L; l++) s += p[(size_t)l * DQ];
    g_qs[b * DQ + d] = s;
}

// ---- K2: q_sum[b,o] = qs[b,:] . w_qs_w[o,:] + L*bias[o] ----
// grid (16 o-chunks of 32, 4 b-chunks of 8), block 256: thread=(o_local, bb)
__global__ void k_qproj(const float* __restrict__ w, const float* __restrict__ bias) {
    __shared__ __align__(16) float sq[8 * DQ];           // 32KB
    int oc = blockIdx.x, bstart = blockIdx.y * 8;
    int tid = threadIdx.x;
    const float4* gq = (const float4*)g_qs;
    float4* sq4 = (float4*)sq;
    for (int i = tid; i < 8 * DQ / 4; i += 256) {
        int bb = i >> 8, c4 = i & 255;
        sq4[bb * 256 + c4] = gq[(size_t)(bstart + bb) * 256 + c4];
    }
    __syncthreads();
    int o_local = tid >> 3, bb = tid & 7;
    int o = oc * 32 + o_local;
    const float4* wr = (const float4*)(w + (size_t)o * DQ);
    const float4* qr = (const float4*)(sq + bb * DQ);
    float acc = (float)L * bias[o];
#pragma unroll 4
    for (int k = 0; k < DQ / 4; k++) {
        float4 a = wr[k], x = qr[k];
        acc += a.x * x.x + a.y * x.y + a.z * x.z + a.w * x.w;
    }
    g_qsum[(bstart + bb) * C + o] = acc;
}

// ---- K3: wq_c[b,n,c] = sum_d w_kc[n*64+d, c] * q_sum[b, n*64+d]; plus bias dots ----
// grid (8 n, 4 b-chunks of 8), block 512 (c)
__global__ void k_wq(const float* __restrict__ wkc, const float* __restrict__ bkc,
                     const float* __restrict__ wkd, const float* __restrict__ bkd) {
    __shared__ float sq[8][DK];
    int n = blockIdx.x, bstart = blockIdx.y * 8;
    int c = threadIdx.x;
    if (c < 8 * DK) {
        int bb = c >> 6, d = c & 63;
        sq[bb][d] = g_qsum[(bstart + bb) * C + n * DK + d];
    }
    __syncthreads();
    float ac[8], ad[8];
#pragma unroll
    for (int bb = 0; bb < 8; bb++) { ac[bb] = 0.f; ad[bb] = 0.f; }
#pragma unroll 2
    for (int d = 0; d < DK; d++) {
        float wc = wkc[(size_t)(n * DK + d) * C + c];
        float wd = wkd[(size_t)(n * DK + d) * C + c];
#pragma unroll
        for (int bb = 0; bb < 8; bb++) {
            ac[bb] += wc * sq[bb][d];
            ad[bb] += wd * sq[bb][d];
        }
    }
#pragma unroll
    for (int bb = 0; bb < 8; bb++) {
        int bn = (bstart + bb) * NH + n;
        g_wqc[(size_t)bn * C + c] = ac[bb];
        g_wqd[(size_t)bn * C + c] = ad[bb];
    }
    if (c < 8) {                         // bias dots: one thread per b
        float s1 = 0.f, s2 = 0.f;
        for (int d = 0; d < DK; d++) {
            s1 += bkc[n * DK + d] * sq[c][d];
            s2 += bkd[n * DK + d] * sq[c][d];
        }
        int bn = (bstart + c) * NH + n;
        g_bqc[bn] = s1; g_bqd[bn] = s2;
    }
}

// ---- K4a: score_c[b,n,s], dif[b,n,s]=sigmoid(score_d) ----
// grid (B, 8 s-chunks of 128), block 128
__global__ void k_scores(const float* __restrict__ v) {
    __shared__ __align__(16) float swc[NH * C];
    __shared__ __align__(16) float swd[NH * C];
    int b = blockIdx.x;
    int s = blockIdx.y * 128 + threadIdx.x;
    const float4* gc = (const float4*)(g_wqc + (size_t)b * NH * C);
    const float4* gd = (const float4*)(g_wqd + (size_t)b * NH * C);
    float4* sc4 = (float4*)swc; float4* sd4 = (float4*)swd;
    for (int i = threadIdx.x; i < NH * C / 4; i += 128) { sc4[i] = gc[i]; sd4[i] = gd[i]; }
    __syncthreads();
    float ac[NH], ad[NH];
#pragma unroll
    for (int n = 0; n < NH; n++) { ac[n] = 0.f; ad[n] = 0.f; }
    const float* vp = v + (size_t)b * C * HW + s;
#pragma unroll 1
    for (int c0 = 0; c0 < C; c0 += 8) {
        float vv[8];
#pragma unroll
        for (int u = 0; u < 8; u++) vv[u] = vp[(size_t)(c0 + u) * HW];
#pragma unroll
        for (int u = 0; u < 8; u++) {
#pragma unroll
            for (int n = 0; n < NH; n++) {
                ac[n] += vv[u] * swc[n * C + c0 + u];
                ad[n] += vv[u] * swd[n * C + c0 + u];
            }
        }
    }
#pragma unroll
    for (int n = 0; n < NH; n++) {
        int bn = b * NH + n;
        g_score[(size_t)bn * HW + s] = (ac[n] + g_bqc[bn]) * TEMP_INV;
        float x = (ad[n] + g_bqd[bn]) * TEMP_INV;
        g_dif[(size_t)bn * HW + s] = 1.f / (1.f + expf(-x));
    }
}

// ---- K4b: p = softmax_s(score_c) ----
__global__ void k_softmax() {
    __shared__ float red[8];
    int bn = blockIdx.x, t = threadIdx.x;    // 256 threads, 4 s each
    const float4* sc = (const float4*)(g_score + (size_t)bn * HW);
    float4 x = sc[t];
    float m = fmaxf(fmaxf(x.x, x.y), fmaxf(x.z, x.w));
#pragma unroll
    for (int o = 16; o; o >>= 1) m = fmaxf(m, __shfl_xor_sync(0xffffffffu, m, o));
    if ((t & 31) == 0) red[t >> 5] = m;
    __syncthreads();
    float M = red[0];
#pragma unroll
    for (int i = 1; i < 8; i++) M = fmaxf(M, red[i]);
    float e0 = expf(x.x - M), e1 = expf(x.y - M), e2 = expf(x.z - M), e3 = expf(x.w - M);
    float s = e0 + e1 + e2 + e3;
#pragma unroll
    for (int o = 16; o; o >>= 1) s += __shfl_xor_sync(0xffffffffu, s, o);
    __syncthreads();
    if ((t & 31) == 0) red[t >> 5] = s;
    __syncthreads();
    float S = 0.f;
#pragma unroll
    for (int i = 0; i < 8; i++) S += red[i];
    float inv = 1.f / S;
    float4 o4 = make_float4(e0 * inv, e1 * inv, e2 * inv, e3 * inv);
    ((float4*)(g_p + (size_t)bn * HW))[t] = o4;
}

// ---- K5: vbar[b,n,c] = sum_s p[b,n,s] * v[b,c,s] ----
// grid (B, 8 c-chunks of 64), block 256 (8 warps, 8 rows each)
__global__ void k_vbar(const float* __restrict__ v) {
    __shared__ __align__(16) float sp[NH * HW];          // 32KB
    int b = blockIdx.x;
    const float4* gp = (const float4*)(g_p + (size_t)b * NH * HW);
    float4* sp4 = (float4*)sp;
    for (int i = threadIdx.x; i < NH * HW / 4; i += 256) sp4[i] = gp[i];
    __syncthreads();
    int warp = threadIdx.x >> 5, lane = threadIdx.x & 31;
#pragma unroll 1
    for (int r = 0; r < 8; r++) {
        int c = blockIdx.y * 64 + r * 8 + warp;
        const float4* vp = (const float4*)(v + (size_t)(b * C + c) * HW);
        float acc[NH];
#pragma unroll
        for (int n = 0; n < NH; n++) acc[n] = 0.f;
#pragma unroll
        for (int it = 0; it < 8; it++) {
            int s4 = it * 32 + lane;
            float4 vv = vp[s4];
#pragma unroll
            for (int n = 0; n < NH; n++) {
                float4 pp = ((const float4*)(sp + n * HW))[s4];
                acc[n] += vv.x * pp.x + vv.y * pp.y + vv.z * pp.z + vv.w * pp.w;
            }
        }
#pragma unroll
        for (int n = 0; n < NH; n++) {
#pragma unroll
            for (int o = 16; o; o >>= 1) acc[n] += __shfl_xor_sync(0xffffffffu, acc[n], o);
        }
        if (lane == 0) {
#pragma unroll
            for (int n = 0; n < NH; n++) g_vbar[(size_t)(b * NH + n) * C + c] = acc[n];
        }
    }
}

// ---- K6: attn[b,o] = w_vs[o,:].vbar[b,head(o),:]+bias ----
// grid (8 n, 2 b-chunks of 16), block 512: thread=(o_local 64, bgrp 8) x 2 b
__global__ void k_attn(const float* __restrict__ wvs, const float* __restrict__ bvs) {
    __shared__ __align__(16) float svb[16 * C];          // 32KB
    int n = blockIdx.x, bstart = blockIdx.y * 16;
    int tid = threadIdx.x;
    const float4* gv = (const float4*)g_vbar;
    float4* s4 = (float4*)svb;
    for (int i = tid; i < 16 * C / 4; i += 512) {
        int bb = i >> 7, c4 = i & 127;
        s4[bb * 128 + c4] = gv[(size_t)((bstart + bb) * NH + n) * 128 + c4];
    }
    __syncthreads();
    int o_local = tid >> 3, bgrp = tid & 7;
    int o = n * DK + o_local;
    const float4* wr = (const float4*)(wvs + (size_t)o * C);
    float acc0 = bvs[o], acc1 = acc0;
    const float4* v0 = (const float4*)(svb + bgrp * C);
    const float4* v1 = (const float4*)(svb + (bgrp + 8) * C);
#pragma unroll 4
    for (int k = 0; k < C / 4; k++) {
        float4 a = wr[k];
        float4 x0 = v0[k], x1 = v1[k];
        acc0 += a.x * x0.x + a.y * x0.y + a.z * x0.z + a.w * x0.w;
        acc1 += a.x * x1.x + a.y * x1.y + a.z * x1.z + a.w * x1.w;
    }
    g_attn[(bstart + bgrp) * C + o] = acc0;
    g_attn[(bstart + bgrp + 8) * C + o] = acc1;
}

// ---- K7: out + attn_map (the big streamer) ----
__global__ void k_out(const float* __restrict__ v, const float* __restrict__ gam,
                      const float* __restrict__ bet, const float* __restrict__ mean,
                      const float* __restrict__ var, float* __restrict__ out,
                      float* __restrict__ amap) {
    __shared__ float sd[HW + HW / 32];   // padded: s -> s + (s>>5)
    int bc = blockIdx.x;                  // b*512 + c
    int b = bc >> 9, c = bc & 511, n = c >> 6;
    int t4 = threadIdx.x * 4;
    const float* gdif = g_dif + (size_t)(b * NH + n) * HW;
#pragma unroll
    for (int u = 0; u < 4; u++) { int s = t4 + u; sd[s + (s >> 5)] = gdif[s]; }
    float a  = g_attn[b * C + c];
    float sc = gam[c] * rsqrtf(var[c] + 1e-5f);
    float mn = mean[c], bt = bet[c];
    __syncthreads();
    size_t base = (size_t)bc * HW + t4;
    float4 rv = *(const float4*)(v + base);
    const float* rvp = (const float*)&rv;
    float vals[4], os[4];
#pragma unroll
    for (int u = 0; u < 4; u++) {
        int t = t4 + u;
        int i = t >> 5, j = t & 31;
        float dd = sd[j * 33 + i];   // padded transpose read, conflict-free
        float val = dd * a;
        vals[u] = val;
        float o2 = (val - mn) * sc + bt + rvp[u];
        os[u] = o2 >= 0.f ? o2 : 0.1f * o2;
    }
    *(float4*)(amap + base) = *(float4*)vals;
    *(float4*)(out  + base) = *(float4*)os;
}

// ---- K8: m_attn; A9 computed inline from g_attn ----
__global__ void k_m(const float* __restrict__ wm, const float* __restrict__ wmb,
                    float* __restrict__ m) {
    __shared__ float sd[NH][HW + 32];
    __shared__ float sA[NH * 9];
    int b = blockIdx.x, t = threadIdx.x;   // 1024 threads
    for (int n = 0; n < NH; n++) { int s = t; sd[n][s + (s >> 5)] = g_dif[(size_t)(b * NH + n) * HW + s]; }
    if (t < NH * 9) {
        int nn = t / 9, k = t - nn * 9;
        float a = 0.f;
        for (int d = 0; d < DK; d++)
            a += g_attn[b * C + nn * DK + d] * wm[(size_t)(nn * DK + d) * 9 + k];
        sA[t] = a;
    }
    __syncthreads();
    int i = t >> 5, j = t & 31;
    float acc = wmb[0];
#pragma unroll
    for (int n = 0; n < NH; n++) {
#pragma unroll
        for (int ki = 0; ki < 3; ki++) {
            int ii = i + ki - 1;
            if (ii < 0 || ii >= 32) continue;
#pragma unroll
            for (int kj = 0; kj < 3; kj++) {
                int jj = j + kj - 1;
                if (jj < 0 || jj >= 32) continue;
                acc += sA[n * 9 + ki * 3 + kj] * sd[n][jj * 33 + ii];
            }
        }
    }
    m[b * HW + i * 32 + j] = acc;
}

extern "C" void kernel_launch(void* const* d_in, const int* in_sizes, int n_in,
                              void* d_out, int out_size) {
    (void)in_sizes; (void)n_in; (void)out_size;
    const float* q      = (const float*)d_in[0];
    const float* v      = (const float*)d_in[1];
    // d_in[2] = mask — unused (softmax over size-1 axis == 1)
    const float* w_qs_w = (const float*)d_in[3];
    const float* w_qs_b = (const float*)d_in[4];
    // d_in[5], d_in[6] = w_qs_att_* — unused for the same reason
    const float* w_kc_w = (const float*)d_in[7];
    const float* w_kc_b = (const float*)d_in[8];
    const float* w_kd_w = (const float*)d_in[9];
    const float* w_kd_b = (const float*)d_in[10];
    const float* w_vs_w = (const float*)d_in[11];
    const float* w_vs_b = (const float*)d_in[12];
    const float* w_m_w  = (const float*)d_in[13];
    const float* w_m_b  = (const float*)d_in[14];
    const float* bn_g   = (const float*)d_in[15];
    const float* bn_b   = (const float*)d_in[16];
    const float* bn_m   = (const float*)d_in[17];
    const float* bn_v   = (const float*)d_in[18];

    float* out    = (float*)d_out;
    float* m_attn = out + (size_t)B * C * HW;        // 16,777,216
    float* amap   = m_attn + (size_t)B * HW;         // +32,768

    k_qsum_l <<<dim3(B, 2), 512>>>(q);
    k_qproj  <<<dim3(16, 4), 256>>>(w_qs_w, w_qs_b);
    k_wq     <<<dim3(NH, 4), 512>>>(w_kc_w, w_kc_b, w_kd_w, w_kd_b);
    k_scores <<<dim3(B, 8), 128>>>(v);
    k_softmax<<<B * NH, 256>>>();
    k_vbar   <<<dim3(B, 8), 256>>>(v);
    k_attn   <<<dim3(NH, 2), 512>>>(w_vs_w, w_vs_b);
    k_out    <<<B * C, 256>>>(v, bn_g, bn_b, bn_m, bn_v, out, amap);
    k_m      <<<B, 1024>>>(w_m_w, w_m_b, m_attn);
}

// round 3
// speedup vs baseline: 1.5334x; 1.4028x over previous
#include <cuda_runtime.h>
#include <math.h>

#define B   32
#define L   64
#define DQ  1024
#define C   512
#define NH  8
#define DK  64
#define HW  1024
#define TEMP_INV 0.125f   // 1/sqrt(64)

typedef unsigned long long ull;

__device__ __forceinline__ ull pack2(float lo, float hi) {
    ull r; asm("mov.b64 %0, {%1,%2};" : "=l"(r) : "f"(lo), "f"(hi)); return r;
}
__device__ __forceinline__ void ffma2(ull& d, ull a, ull b) {
    asm("fma.rn.f32x2 %0, %1, %2, %0;" : "+l"(d) : "l"(a), "l"(b));
}
__device__ __forceinline__ float2 unpack2(ull v) {
    float2 f; asm("mov.b64 {%0,%1}, %2;" : "=f"(f.x), "=f"(f.y) : "l"(v)); return f;
}

// ---------------- scratch ----------------
__device__ __align__(16) float g_qs  [B*DQ];
__device__ __align__(16) float g_qsum[B*C];
__device__ __align__(16) float g_wqc [B*NH*C];
__device__ __align__(16) float g_wqd [B*NH*C];
__device__              float g_bqc [B*NH];
__device__              float g_bqd [B*NH];
__device__ __align__(16) float g_part[4*B*16*HW];   // 8MB: [cchunk][b][out16][s]
__device__ __align__(16) float g_p   [B*NH*HW];
__device__ __align__(16) float g_dif [B*NH*HW];
__device__ __align__(16) float g_vbar[B*NH*C];
__device__ __align__(16) float g_attn[B*C];

// ---- K1: qs[b,dq] = sum_l q[b,l,dq] ----
__global__ void k_qsum_l(const float* __restrict__ q) {
    int b = blockIdx.x;
    int d = blockIdx.y * 512 + threadIdx.x;
    const float* p = q + (size_t)b * L * DQ + d;
    float s = 0.f;
#pragma unroll
    for (int l = 0; l < L; l++) s += p[(size_t)l * DQ];
    g_qs[b * DQ + d] = s;
}

// ---- K2: q_sum[b,o] = qs[b,:] . w_qs_w[o,:] + L*bias[o] ----
__global__ void k_qproj(const float* __restrict__ w, const float* __restrict__ bias) {
    __shared__ __align__(16) float sq[8 * DQ];
    int oc = blockIdx.x, bstart = blockIdx.y * 8;
    int tid = threadIdx.x;
    const float4* gq = (const float4*)g_qs;
    float4* sq4 = (float4*)sq;
    for (int i = tid; i < 8 * DQ / 4; i += 256) {
        int bb = i >> 8, c4 = i & 255;
        sq4[bb * 256 + c4] = gq[(size_t)(bstart + bb) * 256 + c4];
    }
    __syncthreads();
    int o_local = tid >> 3, bb = tid & 7;
    int o = oc * 32 + o_local;
    const float4* wr = (const float4*)(w + (size_t)o * DQ);
    const float4* qr = (const float4*)(sq + bb * DQ);
    float acc = (float)L * bias[o];
#pragma unroll 4
    for (int k = 0; k < DQ / 4; k++) {
        float4 a = wr[k], x = qr[k];
        acc += a.x * x.x + a.y * x.y + a.z * x.z + a.w * x.w;
    }
    g_qsum[(bstart + bb) * C + o] = acc;
}

// ---- K3: wq[b,n,c] + bias dots ----
__global__ void k_wq(const float* __restrict__ wkc, const float* __restrict__ bkc,
                     const float* __restrict__ wkd, const float* __restrict__ bkd) {
    __shared__ float sq[8][DK];
    int n = blockIdx.x, bstart = blockIdx.y * 8;
    int c = threadIdx.x;
    if (c < 8 * DK) {
        int bb = c >> 6, d = c & 63;
        sq[bb][d] = g_qsum[(bstart + bb) * C + n * DK + d];
    }
    __syncthreads();
    float ac[8], ad[8];
#pragma unroll
    for (int bb = 0; bb < 8; bb++) { ac[bb] = 0.f; ad[bb] = 0.f; }
#pragma unroll 2
    for (int d = 0; d < DK; d++) {
        float wc = wkc[(size_t)(n * DK + d) * C + c];
        float wd = wkd[(size_t)(n * DK + d) * C + c];
#pragma unroll
        for (int bb = 0; bb < 8; bb++) {
            ac[bb] += wc * sq[bb][d];
            ad[bb] += wd * sq[bb][d];
        }
    }
#pragma unroll
    for (int bb = 0; bb < 8; bb++) {
        int bn = (bstart + bb) * NH + n;
        g_wqc[(size_t)bn * C + c] = ac[bb];
        g_wqd[(size_t)bn * C + c] = ad[bb];
    }
    if (c < 8) {
        float s1 = 0.f, s2 = 0.f;
        for (int d = 0; d < DK; d++) {
            s1 += bkc[n * DK + d] * sq[c][d];
            s2 += bkd[n * DK + d] * sq[c][d];
        }
        int bn = (bstart + c) * NH + n;
        g_bqc[bn] = s1; g_bqd[bn] = s2;
    }
}

// ---- K4a: partial scores. grid (B, 2 s-halves, 4 c-chunks), block 128 ----
// out k = n (0..7): c-branch; k = 8+n: d-branch. Register tile 4s x 16out, FFMA2.
__global__ void __launch_bounds__(128) k_scores_part(const float* __restrict__ v) {
    __shared__ __align__(16) float sw[128 * 32];   // 16KB, weights duplicated
    int b = blockIdx.x, sh = blockIdx.y, cc = blockIdx.z;
    int tid = threadIdx.x;
    int cbase = cc * 128;
    for (int i = tid; i < 128 * 16; i += 128) {
        int c = i >> 4, k = i & 15;
        float w = (k < 8) ? g_wqc[(size_t)b * NH * C + k * C + cbase + c]
                          : g_wqd[(size_t)b * NH * C + (k - 8) * C + cbase + c];
        sw[c * 32 + 2 * k]     = w;
        sw[c * 32 + 2 * k + 1] = w;
    }
    __syncthreads();
    int s0 = sh * 512 + tid * 4;
    ull acc[16][2];
#pragma unroll
    for (int k = 0; k < 16; k++) { acc[k][0] = 0ull; acc[k][1] = 0ull; }
    const float4* vp = (const float4*)(v + ((size_t)(b * C + cbase)) * HW + s0);
#pragma unroll 1
    for (int c = 0; c < 128; c += 4) {
        float4 vv[4];
#pragma unroll
        for (int u = 0; u < 4; u++) vv[u] = vp[(size_t)(c + u) * (HW / 4)];
#pragma unroll
        for (int u = 0; u < 4; u++) {
            ull v01 = pack2(vv[u].x, vv[u].y);
            ull v23 = pack2(vv[u].z, vv[u].w);
            const ulonglong2* w2 = (const ulonglong2*)(sw + (c + u) * 32);
#pragma unroll
            for (int k4 = 0; k4 < 8; k4++) {
                ulonglong2 wp = w2[k4];
                ffma2(acc[2 * k4][0],     v01, wp.x);
                ffma2(acc[2 * k4][1],     v23, wp.x);
                ffma2(acc[2 * k4 + 1][0], v01, wp.y);
                ffma2(acc[2 * k4 + 1][1], v23, wp.y);
            }
        }
    }
    float* gp = g_part + (((size_t)cc * B + b) * 16) * HW + s0;
#pragma unroll
    for (int k = 0; k < 16; k++) {
        ulonglong2 st; st.x = acc[k][0]; st.y = acc[k][1];
        *(ulonglong2*)(gp + (size_t)k * HW) = st;
    }
}

// ---- K4b: combine partials + bias + softmax (score) + sigmoid (dif) ----
// grid B*NH, block 256, thread = 4 s
__global__ void k_scores_fin() {
    __shared__ float red[8];
    int bn = blockIdx.x, b = bn >> 3, n = bn & 7;
    int t = threadIdx.x, s0 = t * 4;
    float4 sc = make_float4(0.f, 0.f, 0.f, 0.f);
    float4 sd = make_float4(0.f, 0.f, 0.f, 0.f);
#pragma unroll
    for (int cc = 0; cc < 4; cc++) {
        float4 p = *(const float4*)(g_part + (((size_t)cc * B + b) * 16 + n) * HW + s0);
        sc.x += p.x; sc.y += p.y; sc.z += p.z; sc.w += p.w;
        float4 q = *(const float4*)(g_part + (((size_t)cc * B + b) * 16 + 8 + n) * HW + s0);
        sd.x += q.x; sd.y += q.y; sd.z += q.z; sd.w += q.w;
    }
    float bqc = g_bqc[bn], bqd = g_bqd[bn];
    float x0 = (sc.x + bqc) * TEMP_INV, x1 = (sc.y + bqc) * TEMP_INV;
    float x2 = (sc.z + bqc) * TEMP_INV, x3 = (sc.w + bqc) * TEMP_INV;
    // softmax over 1024 s
    float m = fmaxf(fmaxf(x0, x1), fmaxf(x2, x3));
#pragma unroll
    for (int o = 16; o; o >>= 1) m = fmaxf(m, __shfl_xor_sync(0xffffffffu, m, o));
    if ((t & 31) == 0) red[t >> 5] = m;
    __syncthreads();
    float M = red[0];
#pragma unroll
    for (int i = 1; i < 8; i++) M = fmaxf(M, red[i]);
    float e0 = expf(x0 - M), e1 = expf(x1 - M), e2 = expf(x2 - M), e3 = expf(x3 - M);
    float s = e0 + e1 + e2 + e3;
#pragma unroll
    for (int o = 16; o; o >>= 1) s += __shfl_xor_sync(0xffffffffu, s, o);
    __syncthreads();
    if ((t & 31) == 0) red[t >> 5] = s;
    __syncthreads();
    float S = 0.f;
#pragma unroll
    for (int i = 0; i < 8; i++) S += red[i];
    float inv = 1.f / S;
    *(float4*)(g_p + (size_t)bn * HW + s0) = make_float4(e0 * inv, e1 * inv, e2 * inv, e3 * inv);
    // sigmoid branch
    float y0 = (sd.x + bqd) * TEMP_INV, y1 = (sd.y + bqd) * TEMP_INV;
    float y2 = (sd.z + bqd) * TEMP_INV, y3 = (sd.w + bqd) * TEMP_INV;
    float4 dd = make_float4(1.f / (1.f + expf(-y0)), 1.f / (1.f + expf(-y1)),
                            1.f / (1.f + expf(-y2)), 1.f / (1.f + expf(-y3)));
    *(float4*)(g_dif + (size_t)bn * HW + s0) = dd;
}

// ---- K5: vbar[b,n,c] = sum_s p[b,n,s] v[b,c,s]. grid (B,16 c-chunks of 32), block 256 ----
__global__ void __launch_bounds__(256) k_vbar2(const float* __restrict__ v) {
    __shared__ __align__(16) ull sp[4 * HW];       // 32KB: [npair][s] packed (p2n, p2n+1)
    int b = blockIdx.x;
    for (int i = threadIdx.x; i < 4 * HW; i += 256) {
        int np = i >> 10, s = i & 1023;
        float a0 = g_p[(size_t)(b * NH + 2 * np) * HW + s];
        float a1 = g_p[(size_t)(b * NH + 2 * np + 1) * HW + s];
        sp[np * HW + s] = pack2(a0, a1);
    }
    __syncthreads();
    int warp = threadIdx.x >> 5, lane = threadIdx.x & 31;
    int c0 = blockIdx.y * 32 + warp * 4;
    const float* vb = v + (size_t)(b * C + c0) * HW;
    ull acc[4][4];
#pragma unroll
    for (int ci = 0; ci < 4; ci++)
#pragma unroll
        for (int np = 0; np < 4; np++) acc[ci][np] = 0ull;
#pragma unroll 2
    for (int it = 0; it < 32; it++) {
        int s = it * 32 + lane;
        float v0 = vb[s], v1 = vb[HW + s], v2 = vb[2 * HW + s], v3 = vb[3 * HW + s];
        ull vd[4] = { pack2(v0, v0), pack2(v1, v1), pack2(v2, v2), pack2(v3, v3) };
        ull pp[4];
#pragma unroll
        for (int np = 0; np < 4; np++) pp[np] = sp[np * HW + s];
#pragma unroll
        for (int ci = 0; ci < 4; ci++)
#pragma unroll
            for (int np = 0; np < 4; np++) ffma2(acc[ci][np], vd[ci], pp[np]);
    }
#pragma unroll
    for (int ci = 0; ci < 4; ci++) {
#pragma unroll
        for (int np = 0; np < 4; np++) {
            float2 f = unpack2(acc[ci][np]);
#pragma unroll
            for (int o = 16; o; o >>= 1) {
                f.x += __shfl_xor_sync(0xffffffffu, f.x, o);
                f.y += __shfl_xor_sync(0xffffffffu, f.y, o);
            }
            if (lane == 0) {
                g_vbar[(size_t)(b * NH + 2 * np) * C + c0 + ci]     = f.x;
                g_vbar[(size_t)(b * NH + 2 * np + 1) * C + c0 + ci] = f.y;
            }
        }
    }
}

// ---- K6: attn[b,o] = w_vs[o,:].vbar[b,head(o),:]+bias ----
__global__ void k_attn(const float* __restrict__ wvs, const float* __restrict__ bvs) {
    __shared__ __align__(16) float svb[16 * C];
    int n = blockIdx.x, bstart = blockIdx.y * 16;
    int tid = threadIdx.x;
    const float4* gv = (const float4*)g_vbar;
    float4* s4 = (float4*)svb;
    for (int i = tid; i < 16 * C / 4; i += 512) {
        int bb = i >> 7, c4 = i & 127;
        s4[bb * 128 + c4] = gv[(size_t)((bstart + bb) * NH + n) * 128 + c4];
    }
    __syncthreads();
    int o_local = tid >> 3, bgrp = tid & 7;
    int o = n * DK + o_local;
    const float4* wr = (const float4*)(wvs + (size_t)o * C);
    float acc0 = bvs[o], acc1 = acc0;
    const float4* v0 = (const float4*)(svb + bgrp * C);
    const float4* v1 = (const float4*)(svb + (bgrp + 8) * C);
#pragma unroll 4
    for (int k = 0; k < C / 4; k++) {
        float4 a = wr[k];
        float4 x0 = v0[k], x1 = v1[k];
        acc0 += a.x * x0.x + a.y * x0.y + a.z * x0.z + a.w * x0.w;
        acc1 += a.x * x1.x + a.y * x1.y + a.z * x1.z + a.w * x1.w;
    }
    g_attn[(bstart + bgrp) * C + o] = acc0;
    g_attn[(bstart + bgrp + 8) * C + o] = acc1;
}

// ---- K7: out + attn_map (streamer) ----
__global__ void k_out(const float* __restrict__ v, const float* __restrict__ gam,
                      const float* __restrict__ bet, const float* __restrict__ mean,
                      const float* __restrict__ var, float* __restrict__ out,
                      float* __restrict__ amap) {
    __shared__ float sd[HW + HW / 32];
    int bc = blockIdx.x;
    int b = bc >> 9, c = bc & 511, n = c >> 6;
    int t4 = threadIdx.x * 4;
    const float* gdif = g_dif + (size_t)(b * NH + n) * HW;
#pragma unroll
    for (int u = 0; u < 4; u++) { int s = t4 + u; sd[s + (s >> 5)] = gdif[s]; }
    float a  = g_attn[b * C + c];
    float sc = gam[c] * rsqrtf(var[c] + 1e-5f);
    float mn = mean[c], bt = bet[c];
    __syncthreads();
    size_t base = (size_t)bc * HW + t4;
    float4 rv = *(const float4*)(v + base);
    const float* rvp = (const float*)&rv;
    float vals[4], os[4];
#pragma unroll
    for (int u = 0; u < 4; u++) {
        int t = t4 + u;
        int i = t >> 5, j = t & 31;
        float dd = sd[j * 33 + i];
        float val = dd * a;
        vals[u] = val;
        float o2 = (val - mn) * sc + bt + rvp[u];
        os[u] = o2 >= 0.f ? o2 : 0.1f * o2;
    }
    *(float4*)(amap + base) = *(float4*)vals;
    *(float4*)(out  + base) = *(float4*)os;
}

// ---- K8: m_attn; A9 inline ----
__global__ void k_m(const float* __restrict__ wm, const float* __restrict__ wmb,
                    float* __restrict__ m) {
    __shared__ float sd[NH][HW + 32];
    __shared__ float sA[NH * 9];
    int b = blockIdx.x, t = threadIdx.x;
    for (int n = 0; n < NH; n++) { int s = t; sd[n][s + (s >> 5)] = g_dif[(size_t)(b * NH + n) * HW + s]; }
    if (t < NH * 9) {
        int nn = t / 9, k = t - nn * 9;
        float a = 0.f;
        for (int d = 0; d < DK; d++)
            a += g_attn[b * C + nn * DK + d] * wm[(size_t)(nn * DK + d) * 9 + k];
        sA[t] = a;
    }
    __syncthreads();
    int i = t >> 5, j = t & 31;
    float acc = wmb[0];
#pragma unroll
    for (int n = 0; n < NH; n++) {
#pragma unroll
        for (int ki = 0; ki < 3; ki++) {
            int ii = i + ki - 1;
            if (ii < 0 || ii >= 32) continue;
#pragma unroll
            for (int kj = 0; kj < 3; kj++) {
                int jj = j + kj - 1;
                if (jj < 0 || jj >= 32) continue;
                acc += sA[n * 9 + ki * 3 + kj] * sd[n][jj * 33 + ii];
            }
        }
    }
    m[b * HW + i * 32 + j] = acc;
}

extern "C" void kernel_launch(void* const* d_in, const int* in_sizes, int n_in,
                              void* d_out, int out_size) {
    (void)in_sizes; (void)n_in; (void)out_size;
    const float* q      = (const float*)d_in[0];
    const float* v      = (const float*)d_in[1];
    const float* w_qs_w = (const float*)d_in[3];
    const float* w_qs_b = (const float*)d_in[4];
    const float* w_kc_w = (const float*)d_in[7];
    const float* w_kc_b = (const float*)d_in[8];
    const float* w_kd_w = (const float*)d_in[9];
    const float* w_kd_b = (const float*)d_in[10];
    const float* w_vs_w = (const float*)d_in[11];
    const float* w_vs_b = (const float*)d_in[12];
    const float* w_m_w  = (const float*)d_in[13];
    const float* w_m_b  = (const float*)d_in[14];
    const float* bn_g   = (const float*)d_in[15];
    const float* bn_b   = (const float*)d_in[16];
    const float* bn_m   = (const float*)d_in[17];
    const float* bn_v   = (const float*)d_in[18];

    float* out    = (float*)d_out;
    float* m_attn = out + (size_t)B * C * HW;
    float* amap   = m_attn + (size_t)B * HW;

    k_qsum_l     <<<dim3(B, 2), 512>>>(q);
    k_qproj      <<<dim3(16, 4), 256>>>(w_qs_w, w_qs_b);
    k_wq         <<<dim3(NH, 4), 512>>>(w_kc_w, w_kc_b, w_kd_w, w_kd_b);
    k_scores_part<<<dim3(B, 2, 4), 128>>>(v);
    k_scores_fin <<<B * NH, 256>>>();
    k_vbar2      <<<dim3(B, 16), 256>>>(v);
    k_attn       <<<dim3(NH, 2), 512>>>(w_vs_w, w_vs_b);
    k_out        <<<B * C, 256>>>(v, bn_g, bn_b, bn_m, bn_v, out, amap);
    k_m          <<<B, 1024>>>(w_m_w, w_m_b, m_attn);
}

// round 4
// speedup vs baseline: 1.5445x; 1.0073x over previous
#include <cuda_runtime.h>
#include <math.h>

#define B   32
#define L   64
#define DQ  1024
#define C   512
#define NH  8
#define DK  64
#define HW  1024
#define TEMP_INV 0.125f   // 1/sqrt(64)

typedef unsigned long long ull;

__device__ __forceinline__ ull pack2(float lo, float hi) {
    ull r; asm("mov.b64 %0, {%1,%2};" : "=l"(r) : "f"(lo), "f"(hi)); return r;
}
__device__ __forceinline__ void ffma2(ull& d, ull a, ull b) {
    asm("fma.rn.f32x2 %0, %1, %2, %0;" : "+l"(d) : "l"(a), "l"(b));
}
__device__ __forceinline__ float2 unpack2(ull v) {
    float2 f; asm("mov.b64 {%0,%1}, %2;" : "=f"(f.x), "=f"(f.y) : "l"(v)); return f;
}

// ---------------- scratch ----------------
__device__ __align__(16) float g_qs  [B*DQ];
__device__ __align__(16) float g_qsum[B*C];
__device__ __align__(16) float g_wqc [B*NH*C];
__device__ __align__(16) float g_wqd [B*NH*C];
__device__              float g_bqc [B*NH];
__device__              float g_bqd [B*NH];
__device__ __align__(16) float g_part[8*B*HW*16];   // 16MB: [cc][b][s][k16]
__device__ __align__(16) float g_p   [B*HW*NH];     // [b][s][n]  (n fast!)
__device__ __align__(16) float g_dif [B*NH*HW];     // [b][n][s]
__device__ __align__(16) float g_vbar[B*NH*C];
__device__ __align__(16) float g_attn[B*C];

// ---- K1: qs[b,dq] = sum_l q[b,l,dq] ----
__global__ void k_qsum_l(const float* __restrict__ q) {
    int b = blockIdx.x;
    int d = blockIdx.y * 512 + threadIdx.x;
    const float* p = q + (size_t)b * L * DQ + d;
    float s = 0.f;
#pragma unroll
    for (int l = 0; l < L; l++) s += p[(size_t)l * DQ];
    g_qs[b * DQ + d] = s;
}

// ---- K2: q_sum[b,o] = qs[b,:] . w_qs_w[o,:] + L*bias[o] ----
__global__ void k_qproj(const float* __restrict__ w, const float* __restrict__ bias) {
    __shared__ __align__(16) float sq[8 * DQ];
    int oc = blockIdx.x, bstart = blockIdx.y * 8;
    int tid = threadIdx.x;
    const float4* gq = (const float4*)g_qs;
    float4* sq4 = (float4*)sq;
    for (int i = tid; i < 8 * DQ / 4; i += 256) {
        int bb = i >> 8, c4 = i & 255;
        sq4[bb * 256 + c4] = gq[(size_t)(bstart + bb) * 256 + c4];
    }
    __syncthreads();
    int o_local = tid >> 3, bb = tid & 7;
    int o = oc * 32 + o_local;
    const float4* wr = (const float4*)(w + (size_t)o * DQ);
    const float4* qr = (const float4*)(sq + bb * DQ);
    float acc = (float)L * bias[o];
#pragma unroll 8
    for (int k = 0; k < DQ / 4; k++) {
        float4 a = wr[k], x = qr[k];
        acc += a.x * x.x + a.y * x.y + a.z * x.z + a.w * x.w;
    }
    g_qsum[(bstart + bb) * C + o] = acc;
}

// ---- K3: wq[b,n,c] + bias dots ----
__global__ void k_wq(const float* __restrict__ wkc, const float* __restrict__ bkc,
                     const float* __restrict__ wkd, const float* __restrict__ bkd) {
    __shared__ float sq[8][DK];
    int n = blockIdx.x, bstart = blockIdx.y * 8;
    int c = threadIdx.x;
    if (c < 8 * DK) {
        int bb = c >> 6, d = c & 63;
        sq[bb][d] = g_qsum[(bstart + bb) * C + n * DK + d];
    }
    __syncthreads();
    float ac[8], ad[8];
#pragma unroll
    for (int bb = 0; bb < 8; bb++) { ac[bb] = 0.f; ad[bb] = 0.f; }
#pragma unroll 4
    for (int d = 0; d < DK; d++) {
        float wc = wkc[(size_t)(n * DK + d) * C + c];
        float wd = wkd[(size_t)(n * DK + d) * C + c];
#pragma unroll
        for (int bb = 0; bb < 8; bb++) {
            ac[bb] += wc * sq[bb][d];
            ad[bb] += wd * sq[bb][d];
        }
    }
#pragma unroll
    for (int bb = 0; bb < 8; bb++) {
        int bn = (bstart + bb) * NH + n;
        g_wqc[(size_t)bn * C + c] = ac[bb];
        g_wqd[(size_t)bn * C + c] = ad[bb];
    }
    if (c < 8) {
        float s1 = 0.f, s2 = 0.f;
        for (int d = 0; d < DK; d++) {
            s1 += bkc[n * DK + d] * sq[c][d];
            s2 += bkd[n * DK + d] * sq[c][d];
        }
        int bn = (bstart + c) * NH + n;
        g_bqc[bn] = s1; g_bqd[bn] = s2;
    }
}

// ---- K4a: partial scores. grid (B, 2 s-halves, 8 c-chunks of 64), block 256 ----
// Warps 0-3: c-branch (k=0..7). Warps 4-7: d-branch (k=8..15).
// Out-packed: acc[s][kp] holds (out 2kp, out 2kp+1). v duplicated in regs.
__global__ void __launch_bounds__(256) k_scores_part(const float* __restrict__ v) {
    __shared__ __align__(16) float sw[2][64 * 8];   // [grp][c*8+k] 4KB
    int b = blockIdx.x, sh = blockIdx.y, cc = blockIdx.z;
    int tid = threadIdx.x;
    int cbase = cc * 64;
    for (int i = tid; i < 2 * 512; i += 256) {
        int g = i >> 9, idx = i & 511;
        int c = idx & 63, k = idx >> 6;
        float wv = g == 0 ? g_wqc[(size_t)b * NH * C + k * C + cbase + c]
                          : g_wqd[(size_t)b * NH * C + k * C + cbase + c];
        sw[g][c * 8 + k] = wv;
    }
    __syncthreads();
    int grp = tid >> 7, wtid = tid & 127;
    int s0 = sh * 512 + wtid * 4;
    const float* swg = sw[grp];
    const float* vbase = v + ((size_t)(b * C + cbase)) * HW + s0;
    ull acc[4][4];
#pragma unroll
    for (int s = 0; s < 4; s++)
#pragma unroll
        for (int kp = 0; kp < 4; kp++) acc[s][kp] = 0ull;
#pragma unroll 1
    for (int c = 0; c < 64; c += 4) {
        float4 vv[4];
#pragma unroll
        for (int u = 0; u < 4; u++) vv[u] = *(const float4*)(vbase + (size_t)(c + u) * HW);
#pragma unroll
        for (int u = 0; u < 4; u++) {
            ulonglong2 wA = *(const ulonglong2*)(swg + (c + u) * 8);
            ulonglong2 wB = *(const ulonglong2*)(swg + (c + u) * 8 + 4);
            const float* vf = (const float*)&vv[u];
#pragma unroll
            for (int s = 0; s < 4; s++) {
                ull vd = pack2(vf[s], vf[s]);
                ffma2(acc[s][0], vd, wA.x);
                ffma2(acc[s][1], vd, wA.y);
                ffma2(acc[s][2], vd, wB.x);
                ffma2(acc[s][3], vd, wB.y);
            }
        }
    }
    // store: part[cc][b][s][k16], this group's 8 k at offset grp*8
#pragma unroll
    for (int s = 0; s < 4; s++) {
        float* gp = g_part + (((size_t)cc * B + b) * HW + (s0 + s)) * 16 + grp * 8;
        ulonglong2 st0; st0.x = acc[s][0]; st0.y = acc[s][1];
        ulonglong2 st1; st1.x = acc[s][2]; st1.y = acc[s][3];
        *(ulonglong2*)gp = st0;
        *(ulonglong2*)(gp + 4) = st1;
    }
}

// ---- K4b: combine partials + bias + softmax + sigmoid. grid B, block 512, 2 s/thread ----
__global__ void __launch_bounds__(512) k_scores_fin() {
    __shared__ float redm[16][8];
    __shared__ float reds[16][8];
    int b = blockIdx.x, t = threadIdx.x;
    int warp = t >> 5;
    int s0 = t * 2;
    float sums[2][16];
#pragma unroll
    for (int si = 0; si < 2; si++)
#pragma unroll
        for (int k = 0; k < 16; k++) sums[si][k] = 0.f;
#pragma unroll 2
    for (int cc = 0; cc < 8; cc++) {
#pragma unroll
        for (int si = 0; si < 2; si++) {
            const float4* p4 = (const float4*)(g_part + (((size_t)cc * B + b) * HW + s0 + si) * 16);
            float4 a0 = p4[0], a1 = p4[1], a2 = p4[2], a3 = p4[3];
            sums[si][0] += a0.x; sums[si][1] += a0.y; sums[si][2] += a0.z; sums[si][3] += a0.w;
            sums[si][4] += a1.x; sums[si][5] += a1.y; sums[si][6] += a1.z; sums[si][7] += a1.w;
            sums[si][8] += a2.x; sums[si][9] += a2.y; sums[si][10] += a2.z; sums[si][11] += a2.w;
            sums[si][12] += a3.x; sums[si][13] += a3.y; sums[si][14] += a3.z; sums[si][15] += a3.w;
        }
    }
    float x[2][8];
#pragma unroll
    for (int si = 0; si < 2; si++)
#pragma unroll
        for (int n = 0; n < NH; n++)
            x[si][n] = (sums[si][n] + g_bqc[b * NH + n]) * TEMP_INV;
    // max reduce per n
#pragma unroll
    for (int n = 0; n < NH; n++) {
        float m = fmaxf(x[0][n], x[1][n]);
#pragma unroll
        for (int o = 16; o; o >>= 1) m = fmaxf(m, __shfl_xor_sync(0xffffffffu, m, o));
        if ((t & 31) == 0) redm[warp][n] = m;
    }
    __syncthreads();
    float Mn[8];
#pragma unroll
    for (int n = 0; n < NH; n++) {
        float m = redm[0][n];
#pragma unroll
        for (int w = 1; w < 16; w++) m = fmaxf(m, redm[w][n]);
        Mn[n] = m;
    }
    float e[2][8];
#pragma unroll
    for (int n = 0; n < NH; n++) {
        e[0][n] = expf(x[0][n] - Mn[n]);
        e[1][n] = expf(x[1][n] - Mn[n]);
        float s = e[0][n] + e[1][n];
#pragma unroll
        for (int o = 16; o; o >>= 1) s += __shfl_xor_sync(0xffffffffu, s, o);
        if ((t & 31) == 0) reds[warp][n] = s;
    }
    __syncthreads();
    float Sn[8];
#pragma unroll
    for (int n = 0; n < NH; n++) {
        float s = reds[0][n];
#pragma unroll
        for (int w = 1; w < 16; w++) s += reds[w][n];
        Sn[n] = 1.f / s;
    }
#pragma unroll
    for (int si = 0; si < 2; si++) {
        float pv[8];
#pragma unroll
        for (int n = 0; n < NH; n++) pv[n] = e[si][n] * Sn[n];
        float4* dst = (float4*)(g_p + ((size_t)b * HW + s0 + si) * NH);
        dst[0] = make_float4(pv[0], pv[1], pv[2], pv[3]);
        dst[1] = make_float4(pv[4], pv[5], pv[6], pv[7]);
    }
#pragma unroll
    for (int si = 0; si < 2; si++)
#pragma unroll
        for (int n = 0; n < NH; n++) {
            float y = (sums[si][8 + n] + g_bqd[b * NH + n]) * TEMP_INV;
            g_dif[(size_t)(b * NH + n) * HW + s0 + si] = 1.f / (1.f + expf(-y));
        }
}

// ---- K5: vbar[b,n,c] = sum_s p[b,n,s] v[b,c,s]. grid (B,16 c-chunks of 32), block 256 ----
__global__ void __launch_bounds__(256) k_vbar2(const float* __restrict__ v) {
    __shared__ __align__(16) ull sp[4 * HW];       // [npair][s]
    int b = blockIdx.x;
    const ull* gp = (const ull*)(g_p + (size_t)b * HW * NH);
    for (int i = threadIdx.x; i < 4 * HW; i += 256) {
        int s = i >> 2, np = i & 3;
        sp[np * HW + s] = gp[i];
    }
    __syncthreads();
    int warp = threadIdx.x >> 5, lane = threadIdx.x & 31;
    int c0 = blockIdx.y * 32 + warp * 4;
    const float* vb = v + (size_t)(b * C + c0) * HW;
    ull acc[4][4];
#pragma unroll
    for (int ci = 0; ci < 4; ci++)
#pragma unroll
        for (int np = 0; np < 4; np++) acc[ci][np] = 0ull;
#pragma unroll 4
    for (int it = 0; it < 32; it++) {
        int s = it * 32 + lane;
        float v0 = vb[s], v1 = vb[HW + s], v2 = vb[2 * HW + s], v3 = vb[3 * HW + s];
        ull vd[4] = { pack2(v0, v0), pack2(v1, v1), pack2(v2, v2), pack2(v3, v3) };
        ull pp[4];
#pragma unroll
        for (int np = 0; np < 4; np++) pp[np] = sp[np * HW + s];
#pragma unroll
        for (int ci = 0; ci < 4; ci++)
#pragma unroll
            for (int np = 0; np < 4; np++) ffma2(acc[ci][np], vd[ci], pp[np]);
    }
#pragma unroll
    for (int ci = 0; ci < 4; ci++) {
#pragma unroll
        for (int np = 0; np < 4; np++) {
            float2 f = unpack2(acc[ci][np]);
#pragma unroll
            for (int o = 16; o; o >>= 1) {
                f.x += __shfl_xor_sync(0xffffffffu, f.x, o);
                f.y += __shfl_xor_sync(0xffffffffu, f.y, o);
            }
            if (lane == 0) {
                g_vbar[(size_t)(b * NH + 2 * np) * C + c0 + ci]     = f.x;
                g_vbar[(size_t)(b * NH + 2 * np + 1) * C + c0 + ci] = f.y;
            }
        }
    }
}

// ---- K6: attn[b,o] = w_vs[o,:].vbar[b,head(o),:]+bias ----
__global__ void k_attn(const float* __restrict__ wvs, const float* __restrict__ bvs) {
    __shared__ __align__(16) float svb[16 * C];
    int n = blockIdx.x, bstart = blockIdx.y * 16;
    int tid = threadIdx.x;
    const float4* gv = (const float4*)g_vbar;
    float4* s4 = (float4*)svb;
    for (int i = tid; i < 16 * C / 4; i += 512) {
        int bb = i >> 7, c4 = i & 127;
        s4[bb * 128 + c4] = gv[(size_t)((bstart + bb) * NH + n) * 128 + c4];
    }
    __syncthreads();
    int o_local = tid >> 3, bgrp = tid & 7;
    int o = n * DK + o_local;
    const float4* wr = (const float4*)(wvs + (size_t)o * C);
    float acc0 = bvs[o], acc1 = acc0;
    const float4* v0 = (const float4*)(svb + bgrp * C);
    const float4* v1 = (const float4*)(svb + (bgrp + 8) * C);
#pragma unroll 8
    for (int k = 0; k < C / 4; k++) {
        float4 a = wr[k];
        float4 x0 = v0[k], x1 = v1[k];
        acc0 += a.x * x0.x + a.y * x0.y + a.z * x0.z + a.w * x0.w;
        acc1 += a.x * x1.x + a.y * x1.y + a.z * x1.z + a.w * x1.w;
    }
    g_attn[(bstart + bgrp) * C + o] = acc0;
    g_attn[(bstart + bgrp + 8) * C + o] = acc1;
}

// ---- K7: out + attn_map (streamer), 4 c per CTA ----
__global__ void __launch_bounds__(256) k_out(const float* __restrict__ v, const float* __restrict__ gam,
                      const float* __restrict__ bet, const float* __restrict__ mean,
                      const float* __restrict__ var, float* __restrict__ out,
                      float* __restrict__ amap) {
    __shared__ float sd[HW + HW / 32];
    int blk = blockIdx.x;                 // b*128 + cchunk
    int b = blk >> 7, cbase = (blk & 127) * 4, n = cbase >> 6;
    int t4 = threadIdx.x * 4;
    const float* gdif = g_dif + (size_t)(b * NH + n) * HW;
#pragma unroll
    for (int u = 0; u < 4; u++) { int s = t4 + u; sd[s + (s >> 5)] = gdif[s]; }
    __syncthreads();
    int tt = t4;
    int i0 = tt >> 5, j0 = tt & 31;
    float dd[4];
#pragma unroll
    for (int u = 0; u < 4; u++) dd[u] = sd[(j0 + u) * 33 + i0];   // j varies within float4
#pragma unroll
    for (int u = 0; u < 4; u++) {
        int c = cbase + u;
        float a  = g_attn[b * C + c];
        float sc = gam[c] * rsqrtf(var[c] + 1e-5f);
        float mn = mean[c], bt = bet[c];
        size_t base = ((size_t)(b * C + c)) * HW + t4;
        float4 rv = *(const float4*)(v + base);
        const float* rvp = (const float*)&rv;
        float vals[4], os[4];
#pragma unroll
        for (int k = 0; k < 4; k++) {
            float val = dd[k] * a;
            vals[k] = val;
            float o2 = (val - mn) * sc + bt + rvp[k];
            os[k] = o2 >= 0.f ? o2 : 0.1f * o2;
        }
        *(float4*)(amap + base) = *(float4*)vals;
        *(float4*)(out  + base) = *(float4*)os;
    }
}

// ---- K8: m_attn; A9 inline ----
__global__ void k_m(const float* __restrict__ wm, const float* __restrict__ wmb,
                    float* __restrict__ m) {
    __shared__ float sd[NH][HW + 32];
    __shared__ float sA[NH * 9];
    int b = blockIdx.x, t = threadIdx.x;
    for (int n = 0; n < NH; n++) { int s = t; sd[n][s + (s >> 5)] = g_dif[(size_t)(b * NH + n) * HW + s]; }
    if (t < NH * 9) {
        int nn = t / 9, k = t - nn * 9;
        float a = 0.f;
        for (int d = 0; d < DK; d++)
            a += g_attn[b * C + nn * DK + d] * wm[(size_t)(nn * DK + d) * 9 + k];
        sA[t] = a;
    }
    __syncthreads();
    int i = t >> 5, j = t & 31;
    float acc = wmb[0];
#pragma unroll
    for (int n = 0; n < NH; n++) {
#pragma unroll
        for (int ki = 0; ki < 3; ki++) {
            int ii = i + ki - 1;
            if (ii < 0 || ii >= 32) continue;
#pragma unroll
            for (int kj = 0; kj < 3; kj++) {
                int jj = j + kj - 1;
                if (jj < 0 || jj >= 32) continue;
                acc += sA[n * 9 + ki * 3 + kj] * sd[n][jj * 33 + ii];
            }
        }
    }
    m[b * HW + i * 32 + j] = acc;
}

extern "C" void kernel_launch(void* const* d_in, const int* in_sizes, int n_in,
                              void* d_out, int out_size) {
    (void)in_sizes; (void)n_in; (void)out_size;
    const float* q      = (const float*)d_in[0];
    const float* v      = (const float*)d_in[1];
    const float* w_qs_w = (const float*)d_in[3];
    const float* w_qs_b = (const float*)d_in[4];
    const float* w_kc_w = (const float*)d_in[7];
    const float* w_kc_b = (const float*)d_in[8];
    const float* w_kd_w = (const float*)d_in[9];
    const float* w_kd_b = (const float*)d_in[10];
    const float* w_vs_w = (const float*)d_in[11];
    const float* w_vs_b = (const float*)d_in[12];
    const float* w_m_w  = (const float*)d_in[13];
    const float* w_m_b  = (const float*)d_in[14];
    const float* bn_g   = (const float*)d_in[15];
    const float* bn_b   = (const float*)d_in[16];
    const float* bn_m   = (const float*)d_in[17];
    const float* bn_v   = (const float*)d_in[18];

    float* out    = (float*)d_out;
    float* m_attn = out + (size_t)B * C * HW;
    float* amap   = m_attn + (size_t)B * HW;

    k_qsum_l     <<<dim3(B, 2), 512>>>(q);
    k_qproj      <<<dim3(16, 4), 256>>>(w_qs_w, w_qs_b);
    k_wq         <<<dim3(NH, 4), 512>>>(w_kc_w, w_kc_b, w_kd_w, w_kd_b);
    k_scores_part<<<dim3(B, 2, 8), 256>>>(v);
    k_scores_fin <<<B, 512>>>();
    k_vbar2      <<<dim3(B, 16), 256>>>(v);
    k_attn       <<<dim3(NH, 2), 512>>>(w_vs_w, w_vs_b);
    k_out        <<<B * C / 4, 256>>>(v, bn_g, bn_b, bn_m, bn_v, out, amap);
    k_m          <<<B, 1024>>>(w_m_w, w_m_b, m_attn);
}

// round 6
// speedup vs baseline: 1.8276x; 1.1833x over previous
#include <cuda_runtime.h>
#include <math.h>

#define B   32
#define L   64
#define DQ  1024
#define C   512
#define NH  8
#define DK  64
#define HW  1024
#define TEMP_INV 0.125f   // 1/sqrt(64)

typedef unsigned long long ull;

__device__ __forceinline__ ull pack2(float lo, float hi) {
    ull r; asm("mov.b64 %0, {%1,%2};" : "=l"(r) : "f"(lo), "f"(hi)); return r;
}
__device__ __forceinline__ void ffma2(ull& d, ull a, ull b) {
    asm("fma.rn.f32x2 %0, %1, %2, %0;" : "+l"(d) : "l"(a), "l"(b));
}
__device__ __forceinline__ float2 unpack2(ull v) {
    float2 f; asm("mov.b64 {%0,%1}, %2;" : "=f"(f.x), "=f"(f.y) : "l"(v)); return f;
}

// ---------------- scratch ----------------
__device__ __align__(16) float g_qs  [B*DQ];
__device__ __align__(16) float g_qsum[B*C];
__device__ __align__(16) float g_wqc [B*C*NH];      // [b][c][n]
__device__ __align__(16) float g_wqd [B*C*NH];      // [b][c][n]
__device__              float g_bqc [B*NH];
__device__              float g_bqd [B*NH];
__device__ __align__(16) float g_score[B*HW*NH];    // [b][s][n] raw (pre-softmax, scaled)
__device__ __align__(16) float g_red [B*NH*8*2];    // per chunk (max, sumexp)
__device__ __align__(16) float g_dif [B*NH*HW];     // [b][n][s]
__device__ __align__(16) float g_vbar[B*NH*C];
__device__ __align__(16) float g_attn[B*C];

// ---- K1: qs[b,dq] = sum_l q[b,l,dq] ----
__global__ void k_qsum_l(const float* __restrict__ q) {
    int b = blockIdx.x;
    int d = blockIdx.y * 512 + threadIdx.x;
    const float* p = q + (size_t)b * L * DQ + d;
    float s = 0.f;
#pragma unroll
    for (int l = 0; l < L; l++) s += p[(size_t)l * DQ];
    g_qs[b * DQ + d] = s;
}

// ---- K2: q_sum[b,o] = qs[b,:].w[o,:] + L*bias[o]. grid (16 oc, 8 bc of 4), block 128 ----
__global__ void __launch_bounds__(128) k_qproj(const float* __restrict__ w,
                                               const float* __restrict__ bias) {
    __shared__ __align__(16) float sq[4 * (DQ + 4)];
    int oc = blockIdx.x, bstart = blockIdx.y * 4;
    int tid = threadIdx.x;
    for (int i = tid; i < 4 * DQ / 4; i += 128) {
        int bb = i >> 8, c4 = i & 255;
        *(float4*)(sq + bb * (DQ + 4) + c4 * 4) =
            ((const float4*)g_qs)[(size_t)(bstart + bb) * 256 + c4];
    }
    __syncthreads();
    int o_local = tid >> 2, bb = tid & 3;
    int o = oc * 32 + o_local;
    const float4* wr = (const float4*)(w + (size_t)o * DQ);
    const float4* qr = (const float4*)(sq + bb * (DQ + 4));
    float acc = (float)L * bias[o];
#pragma unroll 8
    for (int k = 0; k < DQ / 4; k++) {
        float4 a = wr[k], x = qr[k];
        acc += a.x * x.x + a.y * x.y + a.z * x.z + a.w * x.w;
    }
    g_qsum[(bstart + bb) * C + o] = acc;
}

// ---- K3: wq[b][c][n] + bias dots. grid (NH, 8 bc of 4), block 512 ----
__global__ void __launch_bounds__(512) k_wq(const float* __restrict__ wkc, const float* __restrict__ bkc,
                                            const float* __restrict__ wkd, const float* __restrict__ bkd) {
    __shared__ float sq[4][DK];
    int n = blockIdx.x, bstart = blockIdx.y * 4;
    int c = threadIdx.x;
    if (c < 4 * DK) {
        int bb = c >> 6, d = c & 63;
        sq[bb][d] = g_qsum[(bstart + bb) * C + n * DK + d];
    }
    __syncthreads();
    float ac[4], ad[4];
#pragma unroll
    for (int bb = 0; bb < 4; bb++) { ac[bb] = 0.f; ad[bb] = 0.f; }
#pragma unroll 4
    for (int d = 0; d < DK; d++) {
        float wc = wkc[(size_t)(n * DK + d) * C + c];
        float wd = wkd[(size_t)(n * DK + d) * C + c];
#pragma unroll
        for (int bb = 0; bb < 4; bb++) {
            ac[bb] += wc * sq[bb][d];
            ad[bb] += wd * sq[bb][d];
        }
    }
#pragma unroll
    for (int bb = 0; bb < 4; bb++) {
        size_t idx = ((size_t)(bstart + bb) * C + c) * NH + n;
        g_wqc[idx] = ac[bb];
        g_wqd[idx] = ad[bb];
    }
    if (c < 4) {
        float s1 = 0.f, s2 = 0.f;
        for (int d = 0; d < DK; d++) {
            s1 += bkc[n * DK + d] * sq[c][d];
            s2 += bkd[n * DK + d] * sq[c][d];
        }
        int bn = (bstart + c) * NH + n;
        g_bqc[bn] = s1; g_bqd[bn] = s2;
    }
}

// ---- K4: scores + dif + softmax partials. grid (B, 8 s-chunks of 128), block 256 ----
// grp 0 (warps 0-3): c-branch -> g_score + partial (max,sumexp)
// grp 1 (warps 4-7): d-branch -> g_dif (sigmoid)
__global__ void __launch_bounds__(256) k_scores(const float* __restrict__ v) {
    __shared__ __align__(16) float sw[2][C * NH];    // 32 KB, [c][n]
    __shared__ float redm[4][8], redz[4][8];
    int b = blockIdx.x, sc = blockIdx.y;
    int tid = threadIdx.x, grp = tid >> 7, wtid = tid & 127;
    {
        const float4* src = (const float4*)((grp == 0 ? g_wqc : g_wqd) + (size_t)b * C * NH);
        float4* dst = (float4*)sw[grp];
        for (int i = wtid; i < C * NH / 4; i += 128) dst[i] = src[i];
    }
    __syncthreads();
    int s = sc * 128 + wtid;
    const float* vp = v + (size_t)b * C * HW + s;
    const float* swg = sw[grp];
    ull acc[4] = {0ull, 0ull, 0ull, 0ull};
#pragma unroll 1
    for (int c0 = 0; c0 < C; c0 += 8) {
        float vv[8];
#pragma unroll
        for (int u = 0; u < 8; u++) vv[u] = vp[(size_t)(c0 + u) * HW];
#pragma unroll
        for (int u = 0; u < 8; u++) {
            ull vd = pack2(vv[u], vv[u]);
            ulonglong2 wA = *(const ulonglong2*)(swg + (c0 + u) * NH);
            ulonglong2 wB = *(const ulonglong2*)(swg + (c0 + u) * NH + 4);
            ffma2(acc[0], vd, wA.x); ffma2(acc[1], vd, wA.y);
            ffma2(acc[2], vd, wB.x); ffma2(acc[3], vd, wB.y);
        }
    }
    int bn0 = b * NH;
    if (grp == 1) {
#pragma unroll
        for (int np = 0; np < 4; np++) {
            float2 f = unpack2(acc[np]);
            float y0 = (f.x + g_bqd[bn0 + 2 * np]) * TEMP_INV;
            float y1 = (f.y + g_bqd[bn0 + 2 * np + 1]) * TEMP_INV;
            g_dif[(size_t)(bn0 + 2 * np) * HW + s]     = 1.f / (1.f + expf(-y0));
            g_dif[(size_t)(bn0 + 2 * np + 1) * HW + s] = 1.f / (1.f + expf(-y1));
        }
    } else {
        float x[8];
#pragma unroll
        for (int np = 0; np < 4; np++) {
            float2 f = unpack2(acc[np]);
            x[2 * np]     = (f.x + g_bqc[bn0 + 2 * np]) * TEMP_INV;
            x[2 * np + 1] = (f.y + g_bqc[bn0 + 2 * np + 1]) * TEMP_INV;
        }
        float4* dst = (float4*)(g_score + ((size_t)b * HW + s) * NH);
        dst[0] = make_float4(x[0], x[1], x[2], x[3]);
        dst[1] = make_float4(x[4], x[5], x[6], x[7]);
        int lane = wtid & 31, w = wtid >> 5;
#pragma unroll
        for (int n = 0; n < NH; n++) {
            float mm = x[n];
#pragma unroll
            for (int o = 16; o; o >>= 1) mm = fmaxf(mm, __shfl_xor_sync(0xffffffffu, mm, o));
            float z = expf(x[n] - mm);
#pragma unroll
            for (int o = 16; o; o >>= 1) z += __shfl_xor_sync(0xffffffffu, z, o);
            if (lane == 0) { redm[w][n] = mm; redz[w][n] = z; }
        }
    }
    __syncthreads();
    if (grp == 0 && wtid < 8) {
        int n = wtid;
        float M = redm[0][n];
#pragma unroll
        for (int w = 1; w < 4; w++) M = fmaxf(M, redm[w][n]);
        float Z = 0.f;
#pragma unroll
        for (int w = 0; w < 4; w++) Z += redz[w][n] * expf(redm[w][n] - M);
        *(float2*)(g_red + ((size_t)(bn0 + n) * 8 + sc) * 2) = make_float2(M, Z);
    }
}

// ---- K5: vbar[b,n,c] = sum_s softmax(score)[s,n] * v[b,c,s]. grid (B,16 cc of 32), block 256 ----
__global__ void __launch_bounds__(256) k_vbar(const float* __restrict__ v) {
    __shared__ __align__(16) ull sp[4352];          // swizzled: phys = i + (i>>4), i = s*4+np
    __shared__ float sM[8], sI[8];
    int b = blockIdx.x, t = threadIdx.x;
    if (t < 8) {
        int n = t;
        float M = -1e30f;
        float2 rz[8];
#pragma unroll
        for (int ch = 0; ch < 8; ch++) {
            rz[ch] = *(const float2*)(g_red + ((size_t)(b * NH + n) * 8 + ch) * 2);
            M = fmaxf(M, rz[ch].x);
        }
        float Z = 0.f;
#pragma unroll
        for (int ch = 0; ch < 8; ch++) Z += rz[ch].y * expf(rz[ch].x - M);
        sM[n] = M; sI[n] = 1.f / Z;
    }
    __syncthreads();
    for (int i = t; i < 4096; i += 256) {
        int s = i >> 2, np = i & 3;
        float2 xx = *(const float2*)(g_score + ((size_t)b * HW + s) * NH + 2 * np);
        float e0 = expf(xx.x - sM[2 * np]) * sI[2 * np];
        float e1 = expf(xx.y - sM[2 * np + 1]) * sI[2 * np + 1];
        sp[i + (i >> 4)] = pack2(e0, e1);
    }
    __syncthreads();
    int warp = t >> 5, lane = t & 31;
    int c0 = blockIdx.y * 32 + warp * 4;
    const float* vb = v + (size_t)(b * C + c0) * HW;
    ull acc[4][4];
#pragma unroll
    for (int ci = 0; ci < 4; ci++)
#pragma unroll
        for (int np = 0; np < 4; np++) acc[ci][np] = 0ull;
#pragma unroll 2
    for (int it = 0; it < 8; it++) {
        float4 vv[4];
#pragma unroll
        for (int ci = 0; ci < 4; ci++)
            vv[ci] = *(const float4*)(vb + (size_t)ci * HW + it * 128 + lane * 4);
        int sb = it * 32 + lane;                    // = (s >> 2) for this lane's s block
#pragma unroll
        for (int si = 0; si < 4; si++) {
            int s = it * 128 + lane * 4 + si;
            int phys = 4 * s + sb;
            // 8-byte loads only: phys may be odd, 16B vectors would fault
            ull pA0 = sp[phys];
            ull pA1 = sp[phys + 1];
            ull pB0 = sp[phys + 2];
            ull pB1 = sp[phys + 3];
#pragma unroll
            for (int ci = 0; ci < 4; ci++) {
                float vs = ((const float*)&vv[ci])[si];
                ull vd = pack2(vs, vs);
                ffma2(acc[ci][0], vd, pA0);
                ffma2(acc[ci][1], vd, pA1);
                ffma2(acc[ci][2], vd, pB0);
                ffma2(acc[ci][3], vd, pB1);
            }
        }
    }
#pragma unroll
    for (int ci = 0; ci < 4; ci++) {
#pragma unroll
        for (int np = 0; np < 4; np++) {
            float2 f = unpack2(acc[ci][np]);
#pragma unroll
            for (int o = 16; o; o >>= 1) {
                f.x += __shfl_xor_sync(0xffffffffu, f.x, o);
                f.y += __shfl_xor_sync(0xffffffffu, f.y, o);
            }
            if (lane == 0) {
                g_vbar[(size_t)(b * NH + 2 * np) * C + c0 + ci]     = f.x;
                g_vbar[(size_t)(b * NH + 2 * np + 1) * C + c0 + ci] = f.y;
            }
        }
    }
}

// ---- K6: attn[b,o] = w_vs[o,:].vbar[b,head(o),:]+bias. grid (NH, 8 bc of 4), block 256 ----
__global__ void __launch_bounds__(256) k_attn(const float* __restrict__ wvs,
                                              const float* __restrict__ bvs) {
    __shared__ __align__(16) float svb[4 * (C + 4)];
    int n = blockIdx.x, bstart = blockIdx.y * 4;
    int tid = threadIdx.x;
    for (int i = tid; i < 4 * C / 4; i += 256) {
        int bb = i >> 7, c4 = i & 127;
        *(float4*)(svb + bb * (C + 4) + c4 * 4) =
            ((const float4*)g_vbar)[(size_t)((bstart + bb) * NH + n) * 128 + c4];
    }
    __syncthreads();
    int o_local = tid >> 2, bb = tid & 3;
    int o = n * DK + o_local;
    const float4* wr = (const float4*)(wvs + (size_t)o * C);
    const float4* xr = (const float4*)(svb + bb * (C + 4));
    float acc = bvs[o];
#pragma unroll 8
    for (int k = 0; k < C / 4; k++) {
        float4 a = wr[k], x = xr[k];
        acc += a.x * x.x + a.y * x.y + a.z * x.z + a.w * x.w;
    }
    g_attn[(bstart + bb) * C + o] = acc;
}

// ---- K7: out + attn_map (streamer), 4 c per CTA ----
__global__ void __launch_bounds__(256) k_out(const float* __restrict__ v, const float* __restrict__ gam,
                      const float* __restrict__ bet, const float* __restrict__ mean,
                      const float* __restrict__ var, float* __restrict__ out,
                      float* __restrict__ amap) {
    __shared__ float sd[HW + HW / 32];
    int blk = blockIdx.x;                 // b*128 + cchunk
    int b = blk >> 7, cbase = (blk & 127) * 4, n = cbase >> 6;
    int t4 = threadIdx.x * 4;
    const float* gdif = g_dif + (size_t)(b * NH + n) * HW;
#pragma unroll
    for (int u = 0; u < 4; u++) { int s = t4 + u; sd[s + (s >> 5)] = gdif[s]; }
    __syncthreads();
    int i0 = t4 >> 5, j0 = t4 & 31;
    float dd[4];
#pragma unroll
    for (int u = 0; u < 4; u++) dd[u] = sd[(j0 + u) * 33 + i0];
#pragma unroll
    for (int u = 0; u < 4; u++) {
        int c = cbase + u;
        float a  = g_attn[b * C + c];
        float sc = gam[c] * rsqrtf(var[c] + 1e-5f);
        float mn = mean[c], bt = bet[c];
        size_t base = ((size_t)(b * C + c)) * HW + t4;
        float4 rv = *(const float4*)(v + base);
        const float* rvp = (const float*)&rv;
        float vals[4], os[4];
#pragma unroll
        for (int k = 0; k < 4; k++) {
            float val = dd[k] * a;
            vals[k] = val;
            float o2 = (val - mn) * sc + bt + rvp[k];
            os[k] = o2 >= 0.f ? o2 : 0.1f * o2;
        }
        *(float4*)(amap + base) = *(float4*)vals;
        *(float4*)(out  + base) = *(float4*)os;
    }
}

// ---- K8: m_attn; A9 inline ----
__global__ void k_m(const float* __restrict__ wm, const float* __restrict__ wmb,
                    float* __restrict__ m) {
    __shared__ float sd[NH][HW + 32];
    __shared__ float sA[NH * 9];
    int b = blockIdx.x, t = threadIdx.x;
    for (int n = 0; n < NH; n++) { int s = t; sd[n][s + (s >> 5)] = g_dif[(size_t)(b * NH + n) * HW + s]; }
    if (t < NH * 9) {
        int nn = t / 9, k = t - nn * 9;
        float a = 0.f;
        for (int d = 0; d < DK; d++)
            a += g_attn[b * C + nn * DK + d] * wm[(size_t)(nn * DK + d) * 9 + k];
        sA[t] = a;
    }
    __syncthreads();
    int i = t >> 5, j = t & 31;
    float acc = wmb[0];
#pragma unroll
    for (int n = 0; n < NH; n++) {
#pragma unroll
        for (int ki = 0; ki < 3; ki++) {
            int ii = i + ki - 1;
            if (ii < 0 || ii >= 32) continue;
#pragma unroll
            for (int kj = 0; kj < 3; kj++) {
                int jj = j + kj - 1;
                if (jj < 0 || jj >= 32) continue;
                acc += sA[n * 9 + ki * 3 + kj] * sd[n][jj * 33 + ii];
            }
        }
    }
    m[b * HW + i * 32 + j] = acc;
}

extern "C" void kernel_launch(void* const* d_in, const int* in_sizes, int n_in,
                              void* d_out, int out_size) {
    (void)in_sizes; (void)n_in; (void)out_size;
    const float* q      = (const float*)d_in[0];
    const float* v      = (const float*)d_in[1];
    const float* w_qs_w = (const float*)d_in[3];
    const float* w_qs_b = (const float*)d_in[4];
    const float* w_kc_w = (const float*)d_in[7];
    const float* w_kc_b = (const float*)d_in[8];
    const float* w_kd_w = (const float*)d_in[9];
    const float* w_kd_b = (const float*)d_in[10];
    const float* w_vs_w = (const float*)d_in[11];
    const float* w_vs_b = (const float*)d_in[12];
    const float* w_m_w  = (const float*)d_in[13];
    const float* w_m_b  = (const float*)d_in[14];
    const float* bn_g   = (const float*)d_in[15];
    const float* bn_b   = (const float*)d_in[16];
    const float* bn_m   = (const float*)d_in[17];
    const float* bn_v   = (const float*)d_in[18];

    float* out    = (float*)d_out;
    float* m_attn = out + (size_t)B * C * HW;
    float* amap   = m_attn + (size_t)B * HW;

    k_qsum_l<<<dim3(B, 2), 512>>>(q);
    k_qproj <<<dim3(16, 8), 128>>>(w_qs_w, w_qs_b);
    k_wq    <<<dim3(NH, 8), 512>>>(w_kc_w, w_kc_b, w_kd_w, w_kd_b);
    k_scores<<<dim3(B, 8), 256>>>(v);
    k_vbar  <<<dim3(B, 16), 256>>>(v);
    k_attn  <<<dim3(NH, 8), 256>>>(w_vs_w, w_vs_b);
    k_out   <<<B * C / 4, 256>>>(v, bn_g, bn_b, bn_m, bn_v, out, amap);
    k_m     <<<B, 1024>>>(w_m_w, w_m_b, m_attn);
}

// round 7
// speedup vs baseline: 2.2730x; 1.2437x over previous
#include <cuda_runtime.h>
#include <math.h>

#define B   32
#define L   64
#define DQ  1024
#define C   512
#define NH  8
#define DK  64
#define HW  1024
#define TEMP_INV 0.125f   // 1/sqrt(64)

typedef unsigned long long ull;

__device__ __forceinline__ ull pack2(float lo, float hi) {
    ull r; asm("mov.b64 %0, {%1,%2};" : "=l"(r) : "f"(lo), "f"(hi)); return r;
}
__device__ __forceinline__ void ffma2(ull& d, ull a, ull b) {
    asm("fma.rn.f32x2 %0, %1, %2, %0;" : "+l"(d) : "l"(a), "l"(b));
}
__device__ __forceinline__ float2 unpack2(ull v) {
    float2 f; asm("mov.b64 {%0,%1}, %2;" : "=f"(f.x), "=f"(f.y) : "l"(v)); return f;
}

// ---------------- scratch ----------------
__device__ __align__(16) float g_qs  [B*DQ];
__device__ __align__(16) float g_qsum[B*C];
__device__ __align__(16) float g_wqc [B*C*NH];      // [b][c][n]
__device__ __align__(16) float g_wqd [B*C*NH];      // [b][c][n]
__device__              float g_bqc [B*NH];
__device__              float g_bqd [B*NH];
__device__ __align__(16) float g_score[B*HW*16];    // [b][s][16]: 0-7 c-branch, 8-15 d-branch
__device__ __align__(16) float g_red [B*NH*8*2];    // per chunk (max, sumexp)
__device__ __align__(16) float g_dif [B*NH*HW];     // [b][n][s]
__device__ __align__(16) float g_vbar[B*NH*C];
__device__ __align__(16) float g_attn[B*C];

// ---- K1: qs[b,dq] = sum_l q[b,l,dq] ----
__global__ void k_qsum_l(const float* __restrict__ q) {
    int b = blockIdx.x;
    int d = blockIdx.y * 512 + threadIdx.x;
    const float* p = q + (size_t)b * L * DQ + d;
    float s = 0.f;
#pragma unroll
    for (int l = 0; l < L; l++) s += p[(size_t)l * DQ];
    g_qs[b * DQ + d] = s;
}

// ---- K2: q_sum[b,o] = qs[b,:].w[o,:] + L*bias[o]. grid (16 oc, 8 bc of 4), block 128 ----
__global__ void __launch_bounds__(128) k_qproj(const float* __restrict__ w,
                                               const float* __restrict__ bias) {
    __shared__ __align__(16) float sq[4 * (DQ + 4)];
    int oc = blockIdx.x, bstart = blockIdx.y * 4;
    int tid = threadIdx.x;
    for (int i = tid; i < 4 * DQ / 4; i += 128) {
        int bb = i >> 8, c4 = i & 255;
        *(float4*)(sq + bb * (DQ + 4) + c4 * 4) =
            ((const float4*)g_qs)[(size_t)(bstart + bb) * 256 + c4];
    }
    __syncthreads();
    int o_local = tid >> 2, bb = tid & 3;
    int o = oc * 32 + o_local;
    const float4* wr = (const float4*)(w + (size_t)o * DQ);
    const float4* qr = (const float4*)(sq + bb * (DQ + 4));
    float acc = (float)L * bias[o];
#pragma unroll 8
    for (int k = 0; k < DQ / 4; k++) {
        float4 a = wr[k], x = qr[k];
        acc += a.x * x.x + a.y * x.y + a.z * x.z + a.w * x.w;
    }
    g_qsum[(bstart + bb) * C + o] = acc;
}

// ---- K3: wq[b][c][n] + bias dots. grid (NH, 8 bc of 4), block 512 ----
__global__ void __launch_bounds__(512) k_wq(const float* __restrict__ wkc, const float* __restrict__ bkc,
                                            const float* __restrict__ wkd, const float* __restrict__ bkd) {
    __shared__ float sq[4][DK];
    int n = blockIdx.x, bstart = blockIdx.y * 4;
    int c = threadIdx.x;
    if (c < 4 * DK) {
        int bb = c >> 6, d = c & 63;
        sq[bb][d] = g_qsum[(bstart + bb) * C + n * DK + d];
    }
    __syncthreads();
    float ac[4], ad[4];
#pragma unroll
    for (int bb = 0; bb < 4; bb++) { ac[bb] = 0.f; ad[bb] = 0.f; }
#pragma unroll 4
    for (int d = 0; d < DK; d++) {
        float wc = wkc[(size_t)(n * DK + d) * C + c];
        float wd = wkd[(size_t)(n * DK + d) * C + c];
#pragma unroll
        for (int bb = 0; bb < 4; bb++) {
            ac[bb] += wc * sq[bb][d];
            ad[bb] += wd * sq[bb][d];
        }
    }
#pragma unroll
    for (int bb = 0; bb < 4; bb++) {
        size_t idx = ((size_t)(bstart + bb) * C + c) * NH + n;
        g_wqc[idx] = ac[bb];
        g_wqd[idx] = ad[bb];
    }
    if (c < 4) {
        float s1 = 0.f, s2 = 0.f;
        for (int d = 0; d < DK; d++) {
            s1 += bkc[n * DK + d] * sq[c][d];
            s2 += bkd[n * DK + d] * sq[c][d];
        }
        int bn = (bstart + c) * NH + n;
        g_bqc[bn] = s1; g_bqd[bn] = s2;
    }
}

// ---- K4a: score partials, both branches. grid (B, 2 sh, 8 cc of 64), block 128, 4 s/thread ----
__global__ void __launch_bounds__(128) k_scores_part(const float* __restrict__ v) {
    __shared__ __align__(16) float sw[64 * 16];   // [c][16]: 0-7 wqc, 8-15 wqd. 4KB
    int b = blockIdx.x, sh = blockIdx.y, cc = blockIdx.z;
    int tid = threadIdx.x;
    int cbase = cc * 64;
    for (int i = tid; i < 256; i += 128) {
        int ci = i >> 2, part = i & 3;
        const float* src = ((part < 2) ? g_wqc : g_wqd)
                         + ((size_t)(b * C + cbase + ci)) * NH + (part & 1) * 4;
        *(float4*)(sw + ci * 16 + ((part < 2) ? 0 : 8) + (part & 1) * 4) = *(const float4*)src;
    }
    __syncthreads();
    int s0 = sh * 512 + tid * 4;
    const float* vbase = v + ((size_t)(b * C + cbase)) * HW + s0;
    ull acc[4][8];
#pragma unroll
    for (int si = 0; si < 4; si++)
#pragma unroll
        for (int kp = 0; kp < 8; kp++) acc[si][kp] = 0ull;
    float4 cur[4], nxt[4];
#pragma unroll
    for (int u = 0; u < 4; u++) cur[u] = *(const float4*)(vbase + (size_t)u * HW);
#pragma unroll 2
    for (int cb = 0; cb < 64; cb += 4) {
        if (cb + 4 < 64) {
#pragma unroll
            for (int u = 0; u < 4; u++)
                nxt[u] = *(const float4*)(vbase + (size_t)(cb + 4 + u) * HW);
        }
#pragma unroll
        for (int u = 0; u < 4; u++) {
            const ulonglong2* w2 = (const ulonglong2*)(sw + (cb + u) * 16);
            ulonglong2 wa = w2[0], wb = w2[1], wc = w2[2], wd = w2[3];
            const float* cf = (const float*)&cur[u];
#pragma unroll
            for (int si = 0; si < 4; si++) {
                ull vd = pack2(cf[si], cf[si]);
                ffma2(acc[si][0], vd, wa.x); ffma2(acc[si][1], vd, wa.y);
                ffma2(acc[si][2], vd, wb.x); ffma2(acc[si][3], vd, wb.y);
                ffma2(acc[si][4], vd, wc.x); ffma2(acc[si][5], vd, wc.y);
                ffma2(acc[si][6], vd, wd.x); ffma2(acc[si][7], vd, wd.y);
            }
        }
#pragma unroll
        for (int u = 0; u < 4; u++) cur[u] = nxt[u];
    }
#pragma unroll
    for (int si = 0; si < 4; si++) {
        float* dst = g_score + ((size_t)b * HW + s0 + si) * 16;
#pragma unroll
        for (int kp = 0; kp < 8; kp++) {
            float2 f = unpack2(acc[si][kp]);
            atomicAdd(dst + 2 * kp, f.x);
            atomicAdd(dst + 2 * kp + 1, f.y);
        }
    }
}

// ---- K4b: finalize: bias+scale, per-chunk softmax stats, sigmoid dif. grid (B,8), block 128 ----
__global__ void __launch_bounds__(128) k_sfin() {
    __shared__ float redm[4][8], redz[4][8];
    int b = blockIdx.x, sc = blockIdx.y;
    int tid = threadIdx.x;
    int s = sc * 128 + tid;
    int bn0 = b * NH;
    float4* gs = (float4*)(g_score + ((size_t)b * HW + s) * 16);
    float4 r0 = gs[0], r1 = gs[1], r2 = gs[2], r3 = gs[3];
    float x[8];
    x[0] = (r0.x + g_bqc[bn0 + 0]) * TEMP_INV;
    x[1] = (r0.y + g_bqc[bn0 + 1]) * TEMP_INV;
    x[2] = (r0.z + g_bqc[bn0 + 2]) * TEMP_INV;
    x[3] = (r0.w + g_bqc[bn0 + 3]) * TEMP_INV;
    x[4] = (r1.x + g_bqc[bn0 + 4]) * TEMP_INV;
    x[5] = (r1.y + g_bqc[bn0 + 5]) * TEMP_INV;
    x[6] = (r1.z + g_bqc[bn0 + 6]) * TEMP_INV;
    x[7] = (r1.w + g_bqc[bn0 + 7]) * TEMP_INV;
    gs[0] = make_float4(x[0], x[1], x[2], x[3]);
    gs[1] = make_float4(x[4], x[5], x[6], x[7]);
    int lane = tid & 31, w = tid >> 5;
#pragma unroll
    for (int n = 0; n < NH; n++) {
        float mm = x[n];
#pragma unroll
        for (int o = 16; o; o >>= 1) mm = fmaxf(mm, __shfl_xor_sync(0xffffffffu, mm, o));
        float z = expf(x[n] - mm);
#pragma unroll
        for (int o = 16; o; o >>= 1) z += __shfl_xor_sync(0xffffffffu, z, o);
        if (lane == 0) { redm[w][n] = mm; redz[w][n] = z; }
    }
    // d branch
    float y[8];
    y[0] = (r2.x + g_bqd[bn0 + 0]) * TEMP_INV;
    y[1] = (r2.y + g_bqd[bn0 + 1]) * TEMP_INV;
    y[2] = (r2.z + g_bqd[bn0 + 2]) * TEMP_INV;
    y[3] = (r2.w + g_bqd[bn0 + 3]) * TEMP_INV;
    y[4] = (r3.x + g_bqd[bn0 + 4]) * TEMP_INV;
    y[5] = (r3.y + g_bqd[bn0 + 5]) * TEMP_INV;
    y[6] = (r3.z + g_bqd[bn0 + 6]) * TEMP_INV;
    y[7] = (r3.w + g_bqd[bn0 + 7]) * TEMP_INV;
#pragma unroll
    for (int n = 0; n < NH; n++)
        g_dif[(size_t)(bn0 + n) * HW + s] = 1.f / (1.f + expf(-y[n]));
    __syncthreads();
    if (tid < 8) {
        int n = tid;
        float M = redm[0][n];
#pragma unroll
        for (int ww = 1; ww < 4; ww++) M = fmaxf(M, redm[ww][n]);
        float Z = 0.f;
#pragma unroll
        for (int ww = 0; ww < 4; ww++) Z += redz[ww][n] * expf(redm[ww][n] - M);
        *(float2*)(g_red + ((size_t)(bn0 + n) * 8 + sc) * 2) = make_float2(M, Z);
    }
}

// ---- K5: vbar[b,n,c] = sum_s softmax(score)[s,n] * v[b,c,s]. grid (B,16 cc of 32), block 256 ----
__global__ void __launch_bounds__(256) k_vbar(const float* __restrict__ v) {
    __shared__ __align__(16) ull sp[4352];          // swizzled: phys = i + (i>>4), i = s*4+np
    __shared__ float sM[8], sI[8];
    int b = blockIdx.x, t = threadIdx.x;
    if (t < 8) {
        int n = t;
        float M = -1e30f;
        float2 rz[8];
#pragma unroll
        for (int ch = 0; ch < 8; ch++) {
            rz[ch] = *(const float2*)(g_red + ((size_t)(b * NH + n) * 8 + ch) * 2);
            M = fmaxf(M, rz[ch].x);
        }
        float Z = 0.f;
#pragma unroll
        for (int ch = 0; ch < 8; ch++) Z += rz[ch].y * expf(rz[ch].x - M);
        sM[n] = M; sI[n] = 1.f / Z;
    }
    __syncthreads();
    for (int i = t; i < 4096; i += 256) {
        int s = i >> 2, np = i & 3;
        float2 xx = *(const float2*)(g_score + ((size_t)b * HW + s) * 16 + 2 * np);
        float e0 = expf(xx.x - sM[2 * np]) * sI[2 * np];
        float e1 = expf(xx.y - sM[2 * np + 1]) * sI[2 * np + 1];
        sp[i + (i >> 4)] = pack2(e0, e1);
    }
    __syncthreads();
    int warp = t >> 5, lane = t & 31;
    int c0 = blockIdx.y * 32 + warp * 4;
    const float* vb = v + (size_t)(b * C + c0) * HW;
    ull acc[4][4];
#pragma unroll
    for (int ci = 0; ci < 4; ci++)
#pragma unroll
        for (int np = 0; np < 4; np++) acc[ci][np] = 0ull;
    float4 vv[4], vn[4];
#pragma unroll
    for (int ci = 0; ci < 4; ci++)
        vv[ci] = *(const float4*)(vb + (size_t)ci * HW + lane * 4);
#pragma unroll 1
    for (int it = 0; it < 8; it++) {
        if (it < 7) {
#pragma unroll
            for (int ci = 0; ci < 4; ci++)
                vn[ci] = *(const float4*)(vb + (size_t)ci * HW + (it + 1) * 128 + lane * 4);
        }
        int sb = it * 32 + lane;
#pragma unroll
        for (int si = 0; si < 4; si++) {
            int s = it * 128 + lane * 4 + si;
            int phys = 4 * s + sb;
            ull pA0 = sp[phys];
            ull pA1 = sp[phys + 1];
            ull pB0 = sp[phys + 2];
            ull pB1 = sp[phys + 3];
#pragma unroll
            for (int ci = 0; ci < 4; ci++) {
                float vs = ((const float*)&vv[ci])[si];
                ull vd = pack2(vs, vs);
                ffma2(acc[ci][0], vd, pA0);
                ffma2(acc[ci][1], vd, pA1);
                ffma2(acc[ci][2], vd, pB0);
                ffma2(acc[ci][3], vd, pB1);
            }
        }
#pragma unroll
        for (int ci = 0; ci < 4; ci++) vv[ci] = vn[ci];
    }
#pragma unroll
    for (int ci = 0; ci < 4; ci++) {
#pragma unroll
        for (int np = 0; np < 4; np++) {
            float2 f = unpack2(acc[ci][np]);
#pragma unroll
            for (int o = 16; o; o >>= 1) {
                f.x += __shfl_xor_sync(0xffffffffu, f.x, o);
                f.y += __shfl_xor_sync(0xffffffffu, f.y, o);
            }
            if (lane == 0) {
                g_vbar[(size_t)(b * NH + 2 * np) * C + c0 + ci]     = f.x;
                g_vbar[(size_t)(b * NH + 2 * np + 1) * C + c0 + ci] = f.y;
            }
        }
    }
}

// ---- K6: attn[b,o] = w_vs[o,:].vbar[b,head(o),:]+bias. grid (NH, 8 bc of 4), block 256 ----
__global__ void __launch_bounds__(256) k_attn(const float* __restrict__ wvs,
                                              const float* __restrict__ bvs) {
    __shared__ __align__(16) float svb[4 * (C + 4)];
    int n = blockIdx.x, bstart = blockIdx.y * 4;
    int tid = threadIdx.x;
    for (int i = tid; i < 4 * C / 4; i += 256) {
        int bb = i >> 7, c4 = i & 127;
        *(float4*)(svb + bb * (C + 4) + c4 * 4) =
            ((const float4*)g_vbar)[(size_t)((bstart + bb) * NH + n) * 128 + c4];
    }
    __syncthreads();
    int o_local = tid >> 2, bb = tid & 3;
    int o = n * DK + o_local;
    const float4* wr = (const float4*)(wvs + (size_t)o * C);
    const float4* xr = (const float4*)(svb + bb * (C + 4));
    float acc = bvs[o];
#pragma unroll 8
    for (int k = 0; k < C / 4; k++) {
        float4 a = wr[k], x = xr[k];
        acc += a.x * x.x + a.y * x.y + a.z * x.z + a.w * x.w;
    }
    g_attn[(bstart + bb) * C + o] = acc;
}

// ---- K7: out + attn_map (streamer), 4 c per CTA ----
__global__ void __launch_bounds__(256) k_out(const float* __restrict__ v, const float* __restrict__ gam,
                      const float* __restrict__ bet, const float* __restrict__ mean,
                      const float* __restrict__ var, float* __restrict__ out,
                      float* __restrict__ amap) {
    __shared__ float sd[HW + HW / 32];
    int blk = blockIdx.x;                 // b*128 + cchunk
    int b = blk >> 7, cbase = (blk & 127) * 4, n = cbase >> 6;
    int t4 = threadIdx.x * 4;
    const float* gdif = g_dif + (size_t)(b * NH + n) * HW;
#pragma unroll
    for (int u = 0; u < 4; u++) { int s = t4 + u; sd[s + (s >> 5)] = gdif[s]; }
    __syncthreads();
    int i0 = t4 >> 5, j0 = t4 & 31;
    float dd[4];
#pragma unroll
    for (int u = 0; u < 4; u++) dd[u] = sd[(j0 + u) * 33 + i0];
#pragma unroll
    for (int u = 0; u < 4; u++) {
        int c = cbase + u;
        float a  = g_attn[b * C + c];
        float sc = gam[c] * rsqrtf(var[c] + 1e-5f);
        float mn = mean[c], bt = bet[c];
        size_t base = ((size_t)(b * C + c)) * HW + t4;
        float4 rv = *(const float4*)(v + base);
        const float* rvp = (const float*)&rv;
        float vals[4], os[4];
#pragma unroll
        for (int k = 0; k < 4; k++) {
            float val = dd[k] * a;
            vals[k] = val;
            float o2 = (val - mn) * sc + bt + rvp[k];
            os[k] = o2 >= 0.f ? o2 : 0.1f * o2;
        }
        *(float4*)(amap + base) = *(float4*)vals;
        *(float4*)(out  + base) = *(float4*)os;
    }
}

// ---- K8: m_attn; A9 inline ----
__global__ void k_m(const float* __restrict__ wm, const float* __restrict__ wmb,
                    float* __restrict__ m) {
    __shared__ float sd[NH][HW + 32];
    __shared__ float sA[NH * 9];
    int b = blockIdx.x, t = threadIdx.x;
    for (int n = 0; n < NH; n++) { int s = t; sd[n][s + (s >> 5)] = g_dif[(size_t)(b * NH + n) * HW + s]; }
    if (t < NH * 9) {
        int nn = t / 9, k = t - nn * 9;
        float a = 0.f;
        for (int d = 0; d < DK; d++)
            a += g_attn[b * C + nn * DK + d] * wm[(size_t)(nn * DK + d) * 9 + k];
        sA[t] = a;
    }
    __syncthreads();
    int i = t >> 5, j = t & 31;
    float acc = wmb[0];
#pragma unroll
    for (int n = 0; n < NH; n++) {
#pragma unroll
        for (int ki = 0; ki < 3; ki++) {
            int ii = i + ki - 1;
            if (ii < 0 || ii >= 32) continue;
#pragma unroll
            for (int kj = 0; kj < 3; kj++) {
                int jj = j + kj - 1;
                if (jj < 0 || jj >= 32) continue;
                acc += sA[n * 9 + ki * 3 + kj] * sd[n][jj * 33 + ii];
            }
        }
    }
    m[b * HW + i * 32 + j] = acc;
}

extern "C" void kernel_launch(void* const* d_in, const int* in_sizes, int n_in,
                              void* d_out, int out_size) {
    (void)in_sizes; (void)n_in; (void)out_size;
    const float* q      = (const float*)d_in[0];
    const float* v      = (const float*)d_in[1];
    const float* w_qs_w = (const float*)d_in[3];
    const float* w_qs_b = (const float*)d_in[4];
    const float* w_kc_w = (const float*)d_in[7];
    const float* w_kc_b = (const float*)d_in[8];
    const float* w_kd_w = (const float*)d_in[9];
    const float* w_kd_b = (const float*)d_in[10];
    const float* w_vs_w = (const float*)d_in[11];
    const float* w_vs_b = (const float*)d_in[12];
    const float* w_m_w  = (const float*)d_in[13];
    const float* w_m_b  = (const float*)d_in[14];
    const float* bn_g   = (const float*)d_in[15];
    const float* bn_b   = (const float*)d_in[16];
    const float* bn_m   = (const float*)d_in[17];
    const float* bn_v   = (const float*)d_in[18];

    float* out    = (float*)d_out;
    float* m_attn = out + (size_t)B * C * HW;
    float* amap   = m_attn + (size_t)B * HW;

    void* sc_ptr = nullptr;
    cudaGetSymbolAddress(&sc_ptr, g_score);
    cudaMemsetAsync(sc_ptr, 0, (size_t)B * HW * 16 * sizeof(float), 0);

    k_qsum_l     <<<dim3(B, 2), 512>>>(q);
    k_qproj      <<<dim3(16, 8), 128>>>(w_qs_w, w_qs_b);
    k_wq         <<<dim3(NH, 8), 512>>>(w_kc_w, w_kc_b, w_kd_w, w_kd_b);
    k_scores_part<<<dim3(B, 2, 8), 128>>>(v);
    k_sfin       <<<dim3(B, 8), 128>>>();
    k_vbar       <<<dim3(B, 16), 256>>>(v);
    k_attn       <<<dim3(NH, 8), 256>>>(w_vs_w, w_vs_b);
    k_out        <<<B * C / 4, 256>>>(v, bn_g, bn_b, bn_m, bn_v, out, amap);
    k_m          <<<B, 1024>>>(w_m_w, w_m_b, m_attn);
}